// round 11
// baseline (speedup 1.0000x reference)
#include <cuda_runtime.h>
#include <cuda_fp16.h>
#include <math.h>
#include <float.h>
#include <stdint.h>

#define NN 100000
#define EE 400000
#define GG 32
#define HH 6
#define HD 192
#define NTILES 6256          // ceil(100000/16)=6250, padded to multiple of 8
#define KSTEPS 12            // 192/16
#define SCAN_BLOCKS 196      // ceil(100000/512)

// ---------------- scratch (device globals; no allocations allowed) ----------
__device__ float g_h[NN * HD];
__device__ __half g_qh[NN * HD];
__device__ __half g_kh[NN * HD];
__device__ __half g_vh[NN * HD];
__device__ __half g_sh[NN * HD];
__device__ float g_pool[GG * HD];
__device__ float g_cnt[GG];

// CSR (built once; edge_index constant across layers)
__device__ int g_deg[NN];
__device__ int g_off[NN];
__device__ int g_cur[NN];
__device__ int g_bsum[256];
__device__ int2 g_edge[EE];          // (src, edge_weight bits)

// fp16x2 fragment operands for mma.sync, pre-paired as u64 for LDG.64
__device__ unsigned long long g_afrag[(size_t)NTILES * KSTEPS * 2 * 32];   // 38.4MB
__device__ unsigned long long g_wfrag[(size_t)12 * KSTEPS * 24 * 32];      // 0.9MB

// ---------------- helpers ---------------------------------------------------
__device__ __forceinline__ unsigned fp2(float a, float b) {
    unsigned r;
    asm("cvt.rn.f16x2.f32 %0, %1, %2;" : "=r"(r) : "f"(b), "f"(a));
    return r;
}

__device__ __forceinline__ void mma_fp16(float* c, const unsigned* a, const unsigned* b) {
    asm("mma.sync.aligned.m16n8k16.row.col.f32.f16.f16.f32 "
        "{%0,%1,%2,%3}, {%4,%5,%6,%7}, {%8,%9}, {%0,%1,%2,%3};"
        : "+f"(c[0]), "+f"(c[1]), "+f"(c[2]), "+f"(c[3])
        : "r"(a[0]), "r"(a[1]), "r"(a[2]), "r"(a[3]), "r"(b[0]), "r"(b[1]));
}

// block reduce over 192 threads (6 warps)
__device__ __forceinline__ float blk_sum(float v, float* red) {
    int t = threadIdx.x, lane = t & 31, w = t >> 5;
#pragma unroll
    for (int o = 16; o; o >>= 1) v += __shfl_xor_sync(0xffffffffu, v, o);
    __syncthreads();
    if (lane == 0) red[w] = v;
    __syncthreads();
    float s = 0.f;
#pragma unroll
    for (int i = 0; i < 6; i++) s += red[i];
    return s;
}

// ---------------- input projection: h = x @ Wp + bp -------------------------
__global__ void proj_kernel(const float* __restrict__ x,
                            const float* __restrict__ Wp,
                            const float* __restrict__ bp) {
    int i = blockIdx.x * blockDim.x + threadIdx.x;
    if (i >= NN * HD) return;
    int n = i / HD, d = i - n * HD;
    const float* xr = x + n * 4;
    float acc = bp[d];
    acc += xr[0] * Wp[d] + xr[1] * Wp[HD + d] + xr[2] * Wp[2 * HD + d] + xr[3] * Wp[3 * HD + d];
    g_h[i] = acc;
}

// ---------------- CSR build (once per launch) -------------------------------
__global__ void deg_zero_kernel() {
    int i = blockIdx.x * 256 + threadIdx.x;
    if (i < NN) g_deg[i] = 0;
}
__global__ void hist_kernel(const int* __restrict__ dst) {
    int e = blockIdx.x * 256 + threadIdx.x;
    if (e < EE) atomicAdd(&g_deg[dst[e]], 1);
}
__global__ void scan1_kernel() {
    __shared__ int sh[512];
    int i = blockIdx.x * 512 + threadIdx.x;
    int v = (i < NN) ? g_deg[i] : 0;
    sh[threadIdx.x] = v;
    __syncthreads();
#pragma unroll
    for (int o = 1; o < 512; o <<= 1) {
        int t = (threadIdx.x >= o) ? sh[threadIdx.x - o] : 0;
        __syncthreads();
        sh[threadIdx.x] += t;
        __syncthreads();
    }
    if (i < NN) g_off[i] = sh[threadIdx.x] - v;
    if (threadIdx.x == 511) g_bsum[blockIdx.x] = sh[511];
}
__global__ void scan2_kernel() {
    __shared__ int sh[256];
    int v = (threadIdx.x < SCAN_BLOCKS) ? g_bsum[threadIdx.x] : 0;
    sh[threadIdx.x] = v;
    __syncthreads();
#pragma unroll
    for (int o = 1; o < 256; o <<= 1) {
        int t = (threadIdx.x >= o) ? sh[threadIdx.x - o] : 0;
        __syncthreads();
        sh[threadIdx.x] += t;
        __syncthreads();
    }
    g_bsum[threadIdx.x] = sh[threadIdx.x] - v;   // exclusive
}
__global__ void scan3_kernel() {
    int i = blockIdx.x * 256 + threadIdx.x;
    if (i >= NN) return;
    int o = g_off[i] + g_bsum[i >> 9];
    g_off[i] = o;
    g_cur[i] = o;
}
__global__ void scatter_kernel(const int* __restrict__ src, const int* __restrict__ dst,
                               const float* __restrict__ ew) {
    int e = blockIdx.x * 256 + threadIdx.x;
    if (e >= EE) return;
    int d = dst[e];
    int pos = atomicAdd(&g_cur[d], 1);
    g_edge[pos] = make_int2(src[e], __float_as_int(ew[e]));
}

// ---------------- convert h into A-fragment layout (fp16 pairs) -------------
__global__ void split_h_kernel() {
    int t = blockIdx.x * 256 + threadIdx.x;
    int lane = t & 31;
    int p = (t >> 5) & 1;
    int ks = (t >> 6) % KSTEPS;
    int tile = t / (KSTEPS * 2 * 32);
    int row = tile * 16 + (lane >> 2);
    int k = ks * 16 + ((lane & 3) << 1) + (p << 3);
    float x0 = 0.f, x1 = 0.f, x2 = 0.f, x3 = 0.f;
    if (row < NN) {
        const float* q = &g_h[row * HD + k];
        x0 = q[0]; x1 = q[1];
    }
    if (row + 8 < NN) {
        const float* q = &g_h[(row + 8) * HD + k];
        x2 = q[0]; x3 = q[1];
    }
    unsigned lo = fp2(x0, x1);
    unsigned hi = fp2(x2, x3);
    g_afrag[t] = ((unsigned long long)hi << 32) | lo;
}

// ---------------- convert all 12 weight matrices into B-fragment layout -----
__global__ void split_w_kernel(const float* __restrict__ Wq, const float* __restrict__ Wk,
                               const float* __restrict__ Wv, const float* __restrict__ Ws) {
    int t = blockIdx.x * 256 + threadIdx.x;
    if (t >= 12 * KSTEPS * 24 * 32) return;
    int lane = t & 31;
    int nt = (t >> 5) % 24;
    int ks = ((t >> 5) / 24) % KSTEPS;
    int mat = t / (32 * 24 * KSTEPS);
    int n = nt * 8 + (lane >> 2);
    int k = ks * 16 + ((lane & 3) << 1);
    int which = mat & 3, layer = mat >> 2;
    const float* W = (which == 0 ? Wq : which == 1 ? Wk : which == 2 ? Wv : Ws)
                     + (size_t)layer * HD * HD;
    unsigned lo = fp2(W[k * HD + n], W[(k + 1) * HD + n]);
    unsigned hi = fp2(W[(k + 8) * HD + n], W[(k + 9) * HD + n]);
    g_wfrag[t] = ((unsigned long long)hi << 32) | lo;
}

// ---------------- tensor-core GEMM: O = h @ W + b (single-pass fp16) --------
// CTA: 256 thr = 8 warps, 3 CTAs/SM. warp (wm 0..1, wn 0..3): m32 x n48 tile.
__global__ __launch_bounds__(256, 3) void gemm_tc_kernel(
    int layer,
    const float* __restrict__ bq, const float* __restrict__ bk,
    const float* __restrict__ bv, const float* __restrict__ bs) {
    int w = threadIdx.x >> 5, lane = threadIdx.x & 31;
    int wm = w & 1, wn = w >> 1;
    int tile0 = blockIdx.x * 4 + wm * 2;
    int mat = layer * 4 + blockIdx.y;

    float C[2][6][4];
#pragma unroll
    for (int mt = 0; mt < 2; mt++)
#pragma unroll
        for (int nt = 0; nt < 6; nt++)
#pragma unroll
            for (int i = 0; i < 4; i++) C[mt][nt][i] = 0.f;

    const unsigned long long* __restrict__ A = g_afrag;
    const unsigned long long* __restrict__ B =
        g_wfrag + (size_t)mat * KSTEPS * 24 * 32;

#pragma unroll 3
    for (int ks = 0; ks < KSTEPS; ks++) {
        unsigned a[2][4];
#pragma unroll
        for (int mt = 0; mt < 2; mt++) {
            size_t base = (((size_t)(tile0 + mt) * KSTEPS + ks) * 2) * 32 + lane;
            unsigned long long v0 = __ldg(&A[base]);
            unsigned long long v1 = __ldg(&A[base + 32]);
            a[mt][0] = (unsigned)v0; a[mt][1] = (unsigned)(v0 >> 32);
            a[mt][2] = (unsigned)v1; a[mt][3] = (unsigned)(v1 >> 32);
        }
#pragma unroll
        for (int nt = 0; nt < 6; nt++) {
            int ntg = wn * 6 + nt;
            unsigned long long bv = __ldg(&B[((size_t)ks * 24 + ntg) * 32 + lane]);
            unsigned b[2] = {(unsigned)bv, (unsigned)(bv >> 32)};
#pragma unroll
            for (int mt = 0; mt < 2; mt++) mma_fp16(C[mt][nt], a[mt], b);
        }
    }

    const float* Bv = ((blockIdx.y == 0) ? bq : (blockIdx.y == 1) ? bk
                     : (blockIdx.y == 2) ? bv : bs) + layer * HD;
    __half* O = (blockIdx.y == 0) ? g_qh : (blockIdx.y == 1) ? g_kh
              : (blockIdx.y == 2) ? g_vh : g_sh;
#pragma unroll
    for (int mt = 0; mt < 2; mt++) {
        int r0 = (tile0 + mt) * 16 + (lane >> 2);
#pragma unroll
        for (int nt = 0; nt < 6; nt++) {
            int c = (wn * 6 + nt) * 8 + (lane & 3) * 2;
            float b0 = Bv[c], b1 = Bv[c + 1];
            if (r0 < NN)
                *reinterpret_cast<__half2*>(&O[r0 * HD + c]) =
                    __floats2half2_rn(C[mt][nt][0] + b0, C[mt][nt][1] + b1);
            int r1 = r0 + 8;
            if (r1 < NN)
                *reinterpret_cast<__half2*>(&O[r1 * HD + c]) =
                    __floats2half2_rn(C[mt][nt][2] + b0, C[mt][nt][3] + b1);
        }
    }
}

// ---------------- fused node attention: warp per dst node -------------------
// 4-edge batched pipeline; all buffers statically indexed via full unrolls.
__global__ __launch_bounds__(256) void node_attn_kernel(
    const float* __restrict__ lnw, const float* __restrict__ lnb,
    const float* __restrict__ We) {
    int n = blockIdx.x * 8 + (threadIdx.x >> 5);
    int lane = threadIdx.x & 31;
    if (n >= NN) return;
    int off = g_off[n], deg = g_deg[n];

    const __half2* Q2 = (const __half2*)g_qh + (size_t)n * 96;
    const float2* We2 = (const float2*)We;
    float2 q[3], we[3];
#pragma unroll
    for (int j = 0; j < 3; j++) {
        q[j] = __half22float2(Q2[32 * j + lane]);
        we[j] = We2[32 * j + lane];
    }
    float m[3] = {-FLT_MAX, -FLT_MAX, -FLT_MAX};
    float z[3] = {0.f, 0.f, 0.f};
    float2 va[3] = {{0.f, 0.f}, {0.f, 0.f}, {0.f, 0.f}};
    const float scale = 0.17677669529663687f;  // 1/sqrt(32)

    for (int base = 0; base < deg; base += 32) {
        int cnt = min(32, deg - base);
        int2 e = make_int2(0, 0);
        if (lane < cnt) e = __ldg(&g_edge[off + base + lane]);

        int i = 0;
        // ---- 4-edge batched main path ----
        for (; i + 4 <= cnt; i += 4) {
            int su[4]; float wu[4];
#pragma unroll
            for (int u = 0; u < 4; u++) {
                su[u] = __shfl_sync(0xffffffffu, e.x, i + u);
                wu[u] = __int_as_float(__shfl_sync(0xffffffffu, e.y, i + u));
            }
            __half2 kb[4][3];
#pragma unroll
            for (int u = 0; u < 4; u++) {
                const __half2* K2 = (const __half2*)g_kh + (size_t)su[u] * 96;
#pragma unroll
                for (int j = 0; j < 3; j++) kb[u][j] = __ldg(&K2[32 * j + lane]);
            }
            float acc[4][3];
#pragma unroll
            for (int u = 0; u < 4; u++)
#pragma unroll
                for (int j = 0; j < 3; j++) {
                    float2 kf = __half22float2(kb[u][j]);
                    acc[u][j] = q[j].x * (kf.x + wu[u] * we[j].x)
                              + q[j].y * (kf.y + wu[u] * we[j].y);
                }
#pragma unroll
            for (int o = 8; o; o >>= 1)
#pragma unroll
                for (int u = 0; u < 4; u++)
#pragma unroll
                    for (int j = 0; j < 3; j++)
                        acc[u][j] += __shfl_xor_sync(0xffffffffu, acc[u][j], o);

            // v loads in flight while softmax math runs
            __half2 vb[4][3];
#pragma unroll
            for (int u = 0; u < 4; u++) {
                const __half2* V2 = (const __half2*)g_vh + (size_t)su[u] * 96;
#pragma unroll
                for (int j = 0; j < 3; j++) vb[u][j] = __ldg(&V2[32 * j + lane]);
            }
#pragma unroll
            for (int j = 0; j < 3; j++) {
                float l0 = acc[0][j] * scale, l1 = acc[1][j] * scale;
                float l2 = acc[2][j] * scale, l3 = acc[3][j] * scale;
                float gmax = fmaxf(fmaxf(l0, l1), fmaxf(l2, l3));
                float mn = fmaxf(m[j], gmax);
                float corr = __expf(m[j] - mn);
                float p0 = __expf(l0 - mn), p1 = __expf(l1 - mn);
                float p2 = __expf(l2 - mn), p3 = __expf(l3 - mn);
                z[j] = z[j] * corr + (p0 + p1) + (p2 + p3);
                float2 v0 = __half22float2(vb[0][j]), v1 = __half22float2(vb[1][j]);
                float2 v2 = __half22float2(vb[2][j]), v3 = __half22float2(vb[3][j]);
                float ex = p0 * (v0.x + wu[0] * we[j].x) + p1 * (v1.x + wu[1] * we[j].x)
                         + p2 * (v2.x + wu[2] * we[j].x) + p3 * (v3.x + wu[3] * we[j].x);
                float ey = p0 * (v0.y + wu[0] * we[j].y) + p1 * (v1.y + wu[1] * we[j].y)
                         + p2 * (v2.y + wu[2] * we[j].y) + p3 * (v3.y + wu[3] * we[j].y);
                va[j].x = va[j].x * corr + ex;
                va[j].y = va[j].y * corr + ey;
                m[j] = mn;
            }
        }
        // ---- remainder: single-edge ----
        for (; i < cnt; i++) {
            int s = __shfl_sync(0xffffffffu, e.x, i);
            float w = __int_as_float(__shfl_sync(0xffffffffu, e.y, i));
            const __half2* K2 = (const __half2*)g_kh + (size_t)s * 96;
            const __half2* V2 = (const __half2*)g_vh + (size_t)s * 96;
            __half2 kb[3], vb[3];
#pragma unroll
            for (int j = 0; j < 3; j++) {
                kb[j] = __ldg(&K2[32 * j + lane]);
                vb[j] = __ldg(&V2[32 * j + lane]);
            }
            float acc[3];
#pragma unroll
            for (int j = 0; j < 3; j++) {
                float2 kf = __half22float2(kb[j]);
                acc[j] = q[j].x * (kf.x + w * we[j].x) + q[j].y * (kf.y + w * we[j].y);
            }
#pragma unroll
            for (int o = 8; o; o >>= 1)
#pragma unroll
                for (int j = 0; j < 3; j++)
                    acc[j] += __shfl_xor_sync(0xffffffffu, acc[j], o);
#pragma unroll
            for (int j = 0; j < 3; j++) {
                float lgt = acc[j] * scale;
                float mn = fmaxf(m[j], lgt);
                float corr = __expf(m[j] - mn);
                float p = __expf(lgt - mn);
                z[j] = z[j] * corr + p;
                float2 vf = __half22float2(vb[j]);
                va[j].x = va[j].x * corr + p * (vf.x + w * we[j].x);
                va[j].y = va[j].y * corr + p * (vf.y + w * we[j].y);
                m[j] = mn;
            }
        }
    }

    // epilogue: val = va/z + skip; LN over 192 dims; relu; h +=
    const __half2* S2 = (const __half2*)g_sh + (size_t)n * 96;
    float2 val[3];
    float s1 = 0.f;
#pragma unroll
    for (int j = 0; j < 3; j++) {
        float inv = (z[j] > 0.f) ? (1.0f / z[j]) : 0.f;
        float2 sv = __half22float2(S2[32 * j + lane]);
        val[j].x = va[j].x * inv + sv.x;
        val[j].y = va[j].y * inv + sv.y;
        s1 += val[j].x + val[j].y;
    }
#pragma unroll
    for (int o = 16; o; o >>= 1) s1 += __shfl_xor_sync(0xffffffffu, s1, o);
    float mu = s1 * (1.0f / HD);
    float s2 = 0.f;
#pragma unroll
    for (int j = 0; j < 3; j++) {
        float dx = val[j].x - mu, dy = val[j].y - mu;
        s2 += dx * dx + dy * dy;
    }
#pragma unroll
    for (int o = 16; o; o >>= 1) s2 += __shfl_xor_sync(0xffffffffu, s2, o);
    float rstd = rsqrtf(s2 * (1.0f / HD) + 1e-5f);

    const float2* LG2 = (const float2*)lnw;
    const float2* LB2 = (const float2*)lnb;
    float2* H2 = (float2*)g_h + (size_t)n * 96;
#pragma unroll
    for (int j = 0; j < 3; j++) {
        int idx = 32 * j + lane;
        float2 gv = LG2[idx], bv = LB2[idx], hv = H2[idx];
        float yx = (val[j].x - mu) * rstd * gv.x + bv.x;
        float yy = (val[j].y - mu) * rstd * gv.y + bv.y;
        hv.x += fmaxf(yx, 0.f);
        hv.y += fmaxf(yy, 0.f);
        H2[idx] = hv;
    }
}

// ---------------- pooling ----------------------------------------------------
__global__ void pool_init_kernel() {
    int i = blockIdx.x * blockDim.x + threadIdx.x;
    if (i < GG * HD) g_pool[i] = 0.f;
    if (i < GG) g_cnt[i] = 0.f;
}

__global__ void pool_kernel(const int* __restrict__ batch) {
    __shared__ float acc[GG * HD];
    __shared__ float scnt[GG];
    int t = threadIdx.x;  // 192
    for (int i = t; i < GG * HD; i += HD) acc[i] = 0.f;
    if (t < GG) scnt[t] = 0.f;
    __syncthreads();
    int per = (NN + gridDim.x - 1) / gridDim.x;
    int n0 = blockIdx.x * per;
    int n1 = min(n0 + per, NN);
    for (int n = n0; n < n1; n++) {
        int g = batch[n];
        acc[g * HD + t] += g_h[n * HD + t];
        if (t == 0) scnt[g] += 1.f;
    }
    __syncthreads();
    for (int i = t; i < GG * HD; i += HD) atomicAdd(&g_pool[i], acc[i]);
    if (t < GG) atomicAdd(&g_cnt[t], scnt[t]);
}

// ---------------- head MLP (block per graph, 192 threads) -------------------
__global__ void head_kernel(const float* __restrict__ ie,
                            const float* __restrict__ fciW, const float* __restrict__ fcib,
                            const float* __restrict__ fcig, const float* __restrict__ fcilb,
                            const float* __restrict__ fc1W, const float* __restrict__ fc1b,
                            const float* __restrict__ fc1g, const float* __restrict__ fc1lb,
                            const float* __restrict__ fc2W, const float* __restrict__ fc2b,
                            const float* __restrict__ fc2g, const float* __restrict__ fc2lb,
                            const float* __restrict__ fc3W, const float* __restrict__ fc3b,
                            float* __restrict__ out) {
    __shared__ float zin[2 * HD];
    __shared__ float buf[HD];
    __shared__ float red[8];
    int t = threadIdx.x;  // 0..191
    int g = blockIdx.x;

    float cnt = fmaxf(g_cnt[g], 1.f);
    zin[t] = g_pool[g * HD + t] / cnt;

    // fc_initial: Linear(1,192) + LN + ReLU
    float iv = ie[g] * fciW[t] + fcib[t];
    float mu = blk_sum(iv, red) * (1.0f / HD);
    float dv = iv - mu;
    float var = blk_sum(dv * dv, red) * (1.0f / HD);
    float rstd = rsqrtf(var + 1e-5f);
    zin[HD + t] = fmaxf(dv * rstd * fcig[t] + fcilb[t], 0.f);
    __syncthreads();

    // fc1: 384 -> 192, LN, ReLU
    float a = fc1b[t];
    for (int k = 0; k < 2 * HD; k++) a += zin[k] * fc1W[k * HD + t];
    mu = blk_sum(a, red) * (1.0f / HD);
    dv = a - mu;
    var = blk_sum(dv * dv, red) * (1.0f / HD);
    rstd = rsqrtf(var + 1e-5f);
    buf[t] = fmaxf(dv * rstd * fc1g[t] + fc1lb[t], 0.f);
    __syncthreads();

    // fc2: 192 -> 96, LN, ReLU
    float a2 = 0.f;
    if (t < 96) {
        a2 = fc2b[t];
        for (int k = 0; k < HD; k++) a2 += buf[k] * fc2W[k * 96 + t];
    }
    mu = blk_sum(t < 96 ? a2 : 0.f, red) * (1.0f / 96.0f);
    dv = a2 - mu;
    var = blk_sum(t < 96 ? dv * dv : 0.f, red) * (1.0f / 96.0f);
    rstd = rsqrtf(var + 1e-5f);
    float r2 = 0.f;
    if (t < 96) r2 = fmaxf(dv * rstd * fc2g[t] + fc2lb[t], 0.f);

    // fc3: 96 -> 1
    float p3 = (t < 96) ? r2 * fc3W[t] : 0.f;
    float tot = blk_sum(p3, red);
    if (t == 0) out[g] = tot + fc3b[0];
}

// ---------------- launch ------------------------------------------------------
extern "C" void kernel_launch(void* const* d_in, const int* in_sizes, int n_in,
                              void* d_out, int out_size) {
    const float* x    = (const float*)d_in[0];
    const int*   ei   = (const int*)d_in[1];
    const float* ew   = (const float*)d_in[2];
    const int*   batch= (const int*)d_in[3];
    const float* ie   = (const float*)d_in[4];
    const float* Wp   = (const float*)d_in[5];
    const float* bp   = (const float*)d_in[6];
    const float* Wq   = (const float*)d_in[7];
    const float* bq   = (const float*)d_in[8];
    const float* Wk   = (const float*)d_in[9];
    const float* bk   = (const float*)d_in[10];
    const float* Wv   = (const float*)d_in[11];
    const float* bv   = (const float*)d_in[12];
    const float* We   = (const float*)d_in[13];
    const float* Ws   = (const float*)d_in[14];
    const float* bs   = (const float*)d_in[15];
    const float* lng  = (const float*)d_in[16];
    const float* lnb  = (const float*)d_in[17];
    const float* fciW = (const float*)d_in[18];
    const float* fcib = (const float*)d_in[19];
    const float* fcig = (const float*)d_in[20];
    const float* fcilb= (const float*)d_in[21];
    const float* fc1W = (const float*)d_in[22];
    const float* fc1b = (const float*)d_in[23];
    const float* fc1g = (const float*)d_in[24];
    const float* fc1lb= (const float*)d_in[25];
    const float* fc2W = (const float*)d_in[26];
    const float* fc2b = (const float*)d_in[27];
    const float* fc2g = (const float*)d_in[28];
    const float* fc2lb= (const float*)d_in[29];
    const float* fc3W = (const float*)d_in[30];
    const float* fc3b = (const float*)d_in[31];
    float* out = (float*)d_out;

    const int* src = ei;
    const int* dst = ei + EE;

    proj_kernel<<<(NN * HD + 255) / 256, 256>>>(x, Wp, bp);
    split_w_kernel<<<(12 * KSTEPS * 24 * 32 + 255) / 256, 256>>>(Wq, Wk, Wv, Ws);

    // CSR build (edge_index constant across layers)
    deg_zero_kernel<<<(NN + 255) / 256, 256>>>();
    hist_kernel<<<(EE + 255) / 256, 256>>>(dst);
    scan1_kernel<<<SCAN_BLOCKS, 512>>>();
    scan2_kernel<<<1, 256>>>();
    scan3_kernel<<<(NN + 255) / 256, 256>>>();
    scatter_kernel<<<(EE + 255) / 256, 256>>>(src, dst, ew);

    for (int i = 0; i < 3; i++) {
        split_h_kernel<<<NTILES * KSTEPS * 2 * 32 / 256, 256>>>();
        gemm_tc_kernel<<<dim3(NTILES / 4, 4), 256>>>(i, bq, bk, bv, bs);
        node_attn_kernel<<<(NN + 7) / 8, 256>>>(lng + i * HD, lnb + i * HD, We + i * HD);
    }

    pool_init_kernel<<<(GG * HD + 255) / 256, 256>>>();
    pool_kernel<<<512, HD>>>(batch);
    head_kernel<<<GG, HD>>>(ie, fciW, fcib, fcig, fcilb,
                            fc1W, fc1b, fc1g, fc1lb,
                            fc2W, fc2b, fc2g, fc2lb,
                            fc3W, fc3b, out);
}

// round 12
// speedup vs baseline: 1.1038x; 1.1038x over previous
#include <cuda_runtime.h>
#include <cuda_fp16.h>
#include <math.h>
#include <float.h>
#include <stdint.h>

#define NN 100000
#define EE 400000
#define GG 32
#define HH 6
#define HD 192
#define NTILES 6256          // ceil(100000/16)=6250, padded to multiple of 8
#define KSTEPS 12            // 192/16
#define SCAN_BLOCKS 196      // ceil(100000/512)

// ---------------- scratch (device globals; no allocations allowed) ----------
__device__ float g_h[NN * HD];
__device__ __half g_qh[NN * HD];
__device__ __half g_kh[NN * HD];
__device__ __half g_vh[NN * HD];
__device__ __half g_sh[NN * HD];
__device__ float g_pool[GG * HD];
__device__ float g_cnt[GG];

// CSR (built once; edge_index constant across layers)
__device__ int g_deg[NN];
__device__ int g_off[NN];
__device__ int g_cur[NN];
__device__ int g_bsum[256];
__device__ int2 g_edge[EE];          // (src, edge_weight bits)

// fp16x2 fragment operands for mma.sync, pre-paired as u64 for LDG.64
__device__ unsigned long long g_afrag[(size_t)NTILES * KSTEPS * 2 * 32];   // 38.4MB
__device__ unsigned long long g_wfrag[(size_t)12 * KSTEPS * 24 * 32];      // 0.9MB

// ---------------- helpers ---------------------------------------------------
__device__ __forceinline__ unsigned fp2(float a, float b) {
    unsigned r;
    asm("cvt.rn.f16x2.f32 %0, %1, %2;" : "=r"(r) : "f"(b), "f"(a));
    return r;
}

__device__ __forceinline__ void mma_fp16(float* c, const unsigned* a, const unsigned* b) {
    asm("mma.sync.aligned.m16n8k16.row.col.f32.f16.f16.f32 "
        "{%0,%1,%2,%3}, {%4,%5,%6,%7}, {%8,%9}, {%0,%1,%2,%3};"
        : "+f"(c[0]), "+f"(c[1]), "+f"(c[2]), "+f"(c[3])
        : "r"(a[0]), "r"(a[1]), "r"(a[2]), "r"(a[3]), "r"(b[0]), "r"(b[1]));
}

// block reduce over 192 threads (6 warps)
__device__ __forceinline__ float blk_sum(float v, float* red) {
    int t = threadIdx.x, lane = t & 31, w = t >> 5;
#pragma unroll
    for (int o = 16; o; o >>= 1) v += __shfl_xor_sync(0xffffffffu, v, o);
    __syncthreads();
    if (lane == 0) red[w] = v;
    __syncthreads();
    float s = 0.f;
#pragma unroll
    for (int i = 0; i < 6; i++) s += red[i];
    return s;
}

// ---------------- input projection: h = x @ Wp + bp -------------------------
__global__ void proj_kernel(const float* __restrict__ x,
                            const float* __restrict__ Wp,
                            const float* __restrict__ bp) {
    int i = blockIdx.x * blockDim.x + threadIdx.x;
    if (i >= NN * HD) return;
    int n = i / HD, d = i - n * HD;
    const float* xr = x + n * 4;
    float acc = bp[d];
    acc += xr[0] * Wp[d] + xr[1] * Wp[HD + d] + xr[2] * Wp[2 * HD + d] + xr[3] * Wp[3 * HD + d];
    g_h[i] = acc;
}

// ---------------- CSR build (once per launch) -------------------------------
__global__ void deg_zero_kernel() {
    int i = blockIdx.x * 256 + threadIdx.x;
    if (i < NN) g_deg[i] = 0;
}
__global__ void hist_kernel(const int* __restrict__ dst) {
    int e = blockIdx.x * 256 + threadIdx.x;
    if (e < EE) atomicAdd(&g_deg[dst[e]], 1);
}
__global__ void scan1_kernel() {
    __shared__ int sh[512];
    int i = blockIdx.x * 512 + threadIdx.x;
    int v = (i < NN) ? g_deg[i] : 0;
    sh[threadIdx.x] = v;
    __syncthreads();
#pragma unroll
    for (int o = 1; o < 512; o <<= 1) {
        int t = (threadIdx.x >= o) ? sh[threadIdx.x - o] : 0;
        __syncthreads();
        sh[threadIdx.x] += t;
        __syncthreads();
    }
    if (i < NN) g_off[i] = sh[threadIdx.x] - v;
    if (threadIdx.x == 511) g_bsum[blockIdx.x] = sh[511];
}
__global__ void scan2_kernel() {
    __shared__ int sh[256];
    int v = (threadIdx.x < SCAN_BLOCKS) ? g_bsum[threadIdx.x] : 0;
    sh[threadIdx.x] = v;
    __syncthreads();
#pragma unroll
    for (int o = 1; o < 256; o <<= 1) {
        int t = (threadIdx.x >= o) ? sh[threadIdx.x - o] : 0;
        __syncthreads();
        sh[threadIdx.x] += t;
        __syncthreads();
    }
    g_bsum[threadIdx.x] = sh[threadIdx.x] - v;   // exclusive
}
__global__ void scan3_kernel() {
    int i = blockIdx.x * 256 + threadIdx.x;
    if (i >= NN) return;
    int o = g_off[i] + g_bsum[i >> 9];
    g_off[i] = o;
    g_cur[i] = o;
}
__global__ void scatter_kernel(const int* __restrict__ src, const int* __restrict__ dst,
                               const float* __restrict__ ew) {
    int e = blockIdx.x * 256 + threadIdx.x;
    if (e >= EE) return;
    int d = dst[e];
    int pos = atomicAdd(&g_cur[d], 1);
    g_edge[pos] = make_int2(src[e], __float_as_int(ew[e]));
}

// ---------------- convert h into A-fragment layout (fp16 pairs) -------------
__global__ void split_h_kernel() {
    int t = blockIdx.x * 256 + threadIdx.x;
    int lane = t & 31;
    int p = (t >> 5) & 1;
    int ks = (t >> 6) % KSTEPS;
    int tile = t / (KSTEPS * 2 * 32);
    int row = tile * 16 + (lane >> 2);
    int k = ks * 16 + ((lane & 3) << 1) + (p << 3);
    float x0 = 0.f, x1 = 0.f, x2 = 0.f, x3 = 0.f;
    if (row < NN) {
        const float* q = &g_h[row * HD + k];
        x0 = q[0]; x1 = q[1];
    }
    if (row + 8 < NN) {
        const float* q = &g_h[(row + 8) * HD + k];
        x2 = q[0]; x3 = q[1];
    }
    unsigned lo = fp2(x0, x1);
    unsigned hi = fp2(x2, x3);
    g_afrag[t] = ((unsigned long long)hi << 32) | lo;
}

// ---------------- convert all 12 weight matrices into B-fragment layout -----
__global__ void split_w_kernel(const float* __restrict__ Wq, const float* __restrict__ Wk,
                               const float* __restrict__ Wv, const float* __restrict__ Ws) {
    int t = blockIdx.x * 256 + threadIdx.x;
    if (t >= 12 * KSTEPS * 24 * 32) return;
    int lane = t & 31;
    int nt = (t >> 5) % 24;
    int ks = ((t >> 5) / 24) % KSTEPS;
    int mat = t / (32 * 24 * KSTEPS);
    int n = nt * 8 + (lane >> 2);
    int k = ks * 16 + ((lane & 3) << 1);
    int which = mat & 3, layer = mat >> 2;
    const float* W = (which == 0 ? Wq : which == 1 ? Wk : which == 2 ? Wv : Ws)
                     + (size_t)layer * HD * HD;
    unsigned lo = fp2(W[k * HD + n], W[(k + 1) * HD + n]);
    unsigned hi = fp2(W[(k + 8) * HD + n], W[(k + 9) * HD + n]);
    g_wfrag[t] = ((unsigned long long)hi << 32) | lo;
}

// ---------------- tensor-core GEMM: O = h @ W + b (single-pass fp16) --------
// CTA: 256 thr = 8 warps, 3 CTAs/SM. warp (wm 0..1, wn 0..3): m32 x n48 tile.
__global__ __launch_bounds__(256, 3) void gemm_tc_kernel(
    int layer,
    const float* __restrict__ bq, const float* __restrict__ bk,
    const float* __restrict__ bv, const float* __restrict__ bs) {
    int w = threadIdx.x >> 5, lane = threadIdx.x & 31;
    int wm = w & 1, wn = w >> 1;
    int tile0 = blockIdx.x * 4 + wm * 2;
    int mat = layer * 4 + blockIdx.y;

    float C[2][6][4];
#pragma unroll
    for (int mt = 0; mt < 2; mt++)
#pragma unroll
        for (int nt = 0; nt < 6; nt++)
#pragma unroll
            for (int i = 0; i < 4; i++) C[mt][nt][i] = 0.f;

    const unsigned long long* __restrict__ A = g_afrag;
    const unsigned long long* __restrict__ B =
        g_wfrag + (size_t)mat * KSTEPS * 24 * 32;

#pragma unroll 3
    for (int ks = 0; ks < KSTEPS; ks++) {
        unsigned a[2][4];
#pragma unroll
        for (int mt = 0; mt < 2; mt++) {
            size_t base = (((size_t)(tile0 + mt) * KSTEPS + ks) * 2) * 32 + lane;
            unsigned long long v0 = __ldg(&A[base]);
            unsigned long long v1 = __ldg(&A[base + 32]);
            a[mt][0] = (unsigned)v0; a[mt][1] = (unsigned)(v0 >> 32);
            a[mt][2] = (unsigned)v1; a[mt][3] = (unsigned)(v1 >> 32);
        }
#pragma unroll
        for (int nt = 0; nt < 6; nt++) {
            int ntg = wn * 6 + nt;
            unsigned long long bv = __ldg(&B[((size_t)ks * 24 + ntg) * 32 + lane]);
            unsigned b[2] = {(unsigned)bv, (unsigned)(bv >> 32)};
#pragma unroll
            for (int mt = 0; mt < 2; mt++) mma_fp16(C[mt][nt], a[mt], b);
        }
    }

    const float* Bv = ((blockIdx.y == 0) ? bq : (blockIdx.y == 1) ? bk
                     : (blockIdx.y == 2) ? bv : bs) + layer * HD;
    __half* O = (blockIdx.y == 0) ? g_qh : (blockIdx.y == 1) ? g_kh
              : (blockIdx.y == 2) ? g_vh : g_sh;
#pragma unroll
    for (int mt = 0; mt < 2; mt++) {
        int r0 = (tile0 + mt) * 16 + (lane >> 2);
#pragma unroll
        for (int nt = 0; nt < 6; nt++) {
            int c = (wn * 6 + nt) * 8 + (lane & 3) * 2;
            float b0 = Bv[c], b1 = Bv[c + 1];
            if (r0 < NN)
                *reinterpret_cast<__half2*>(&O[r0 * HD + c]) =
                    __floats2half2_rn(C[mt][nt][0] + b0, C[mt][nt][1] + b1);
            int r1 = r0 + 8;
            if (r1 < NN)
                *reinterpret_cast<__half2*>(&O[r1 * HD + c]) =
                    __floats2half2_rn(C[mt][nt][2] + b0, C[mt][nt][3] + b1);
        }
    }
}

// ---------------- fused node attention: HALF-WARP per dst node --------------
// Each 16-lane half processes its own node; lane l owns half2 idx 16j+l
// (head = j). Shared loop to max(deg) with branchless no-op iterations for
// the shorter half. One LDG covers both halves' gathers.
__global__ __launch_bounds__(256, 3) void node_attn_kernel(
    const float* __restrict__ lnw, const float* __restrict__ lnb,
    const float* __restrict__ We) {
    int wid = threadIdx.x >> 5;
    int lane = threadIdx.x & 31;
    int l = lane & 15;
    int half = lane >> 4;
    int n = blockIdx.x * 16 + wid * 2 + half;
    bool nvalid = n < NN;
    int nn = nvalid ? n : 0;
    int off = g_off[nn];
    int deg = nvalid ? g_deg[nn] : 0;
    int dmax = max(deg, __shfl_xor_sync(0xffffffffu, deg, 16));

    const __half2* Q2 = (const __half2*)g_qh + (size_t)nn * 96;
    const float2* We2 = (const float2*)We;
    float2 q[6], we[6];
#pragma unroll
    for (int j = 0; j < 6; j++) {
        q[j] = __half22float2(Q2[16 * j + l]);
        we[j] = We2[16 * j + l];
    }
    float m[6], z[6];
    float2 va[6];
#pragma unroll
    for (int j = 0; j < 6; j++) {
        m[j] = -FLT_MAX; z[j] = 0.f; va[j] = make_float2(0.f, 0.f);
    }
    const float scale = 0.17677669529663687f;  // 1/sqrt(32)

    int2 e = make_int2(0, 0);
    for (int i = 0; i < dmax; i++) {
        if ((i & 15) == 0) {
            e = (i + l < deg) ? __ldg(&g_edge[off + i + l]) : make_int2(0, 0);
        }
        int s = __shfl_sync(0xffffffffu, e.x, i & 15, 16);
        float w = __int_as_float(__shfl_sync(0xffffffffu, e.y, i & 15, 16));
        bool act = i < deg;

        const __half2* K2 = (const __half2*)g_kh + (size_t)s * 96;
        const __half2* V2 = (const __half2*)g_vh + (size_t)s * 96;
        __half2 kb[6], vb[6];
#pragma unroll
        for (int j = 0; j < 6; j++) {
            kb[j] = __ldg(&K2[16 * j + l]);
            vb[j] = __ldg(&V2[16 * j + l]);
        }
        float acc[6];
#pragma unroll
        for (int j = 0; j < 6; j++) {
            float2 kf = __half22float2(kb[j]);
            acc[j] = q[j].x * (kf.x + w * we[j].x) + q[j].y * (kf.y + w * we[j].y);
        }
#pragma unroll
        for (int o = 8; o; o >>= 1)
#pragma unroll
            for (int j = 0; j < 6; j++)
                acc[j] += __shfl_xor_sync(0xffffffffu, acc[j], o, 16);
#pragma unroll
        for (int j = 0; j < 6; j++) {
            float lgt = acc[j] * scale;
            float mn = act ? fmaxf(m[j], lgt) : m[j];
            float corr = __expf(m[j] - mn);       // inactive: exp(0)=1
            float p = act ? __expf(lgt - mn) : 0.f;
            z[j] = z[j] * corr + p;
            float2 vf = __half22float2(vb[j]);
            va[j].x = va[j].x * corr + p * (vf.x + w * we[j].x);
            va[j].y = va[j].y * corr + p * (vf.y + w * we[j].y);
            m[j] = mn;
        }
    }

    if (!nvalid) return;

    // epilogue: val = va/z + skip; LN over 192 dims (16-lane reduce); relu; h+=
    const __half2* S2 = (const __half2*)g_sh + (size_t)n * 96;
    float2 val[6];
    float s1 = 0.f;
#pragma unroll
    for (int j = 0; j < 6; j++) {
        float inv = (z[j] > 0.f) ? (1.0f / z[j]) : 0.f;
        float2 sv = __half22float2(S2[16 * j + l]);
        val[j].x = va[j].x * inv + sv.x;
        val[j].y = va[j].y * inv + sv.y;
        s1 += val[j].x + val[j].y;
    }
#pragma unroll
    for (int o = 8; o; o >>= 1) s1 += __shfl_xor_sync(0xffffffffu, s1, o, 16);
    float mu = s1 * (1.0f / HD);
    float s2 = 0.f;
#pragma unroll
    for (int j = 0; j < 6; j++) {
        float dx = val[j].x - mu, dy = val[j].y - mu;
        s2 += dx * dx + dy * dy;
    }
#pragma unroll
    for (int o = 8; o; o >>= 1) s2 += __shfl_xor_sync(0xffffffffu, s2, o, 16);
    float rstd = rsqrtf(s2 * (1.0f / HD) + 1e-5f);

    const float2* LG2 = (const float2*)lnw;
    const float2* LB2 = (const float2*)lnb;
    float2* H2 = (float2*)g_h + (size_t)n * 96;
#pragma unroll
    for (int j = 0; j < 6; j++) {
        int idx = 16 * j + l;
        float2 gv = LG2[idx], bv = LB2[idx], hv = H2[idx];
        float yx = (val[j].x - mu) * rstd * gv.x + bv.x;
        float yy = (val[j].y - mu) * rstd * gv.y + bv.y;
        hv.x += fmaxf(yx, 0.f);
        hv.y += fmaxf(yy, 0.f);
        H2[idx] = hv;
    }
}

// ---------------- pooling ----------------------------------------------------
__global__ void pool_init_kernel() {
    int i = blockIdx.x * blockDim.x + threadIdx.x;
    if (i < GG * HD) g_pool[i] = 0.f;
    if (i < GG) g_cnt[i] = 0.f;
}

__global__ void pool_kernel(const int* __restrict__ batch) {
    __shared__ float acc[GG * HD];
    __shared__ float scnt[GG];
    int t = threadIdx.x;  // 192
    for (int i = t; i < GG * HD; i += HD) acc[i] = 0.f;
    if (t < GG) scnt[t] = 0.f;
    __syncthreads();
    int per = (NN + gridDim.x - 1) / gridDim.x;
    int n0 = blockIdx.x * per;
    int n1 = min(n0 + per, NN);
    for (int n = n0; n < n1; n++) {
        int g = batch[n];
        acc[g * HD + t] += g_h[n * HD + t];
        if (t == 0) scnt[g] += 1.f;
    }
    __syncthreads();
    for (int i = t; i < GG * HD; i += HD) atomicAdd(&g_pool[i], acc[i]);
    if (t < GG) atomicAdd(&g_cnt[t], scnt[t]);
}

// ---------------- head MLP (block per graph, 192 threads) -------------------
__global__ void head_kernel(const float* __restrict__ ie,
                            const float* __restrict__ fciW, const float* __restrict__ fcib,
                            const float* __restrict__ fcig, const float* __restrict__ fcilb,
                            const float* __restrict__ fc1W, const float* __restrict__ fc1b,
                            const float* __restrict__ fc1g, const float* __restrict__ fc1lb,
                            const float* __restrict__ fc2W, const float* __restrict__ fc2b,
                            const float* __restrict__ fc2g, const float* __restrict__ fc2lb,
                            const float* __restrict__ fc3W, const float* __restrict__ fc3b,
                            float* __restrict__ out) {
    __shared__ float zin[2 * HD];
    __shared__ float buf[HD];
    __shared__ float red[8];
    int t = threadIdx.x;  // 0..191
    int g = blockIdx.x;

    float cnt = fmaxf(g_cnt[g], 1.f);
    zin[t] = g_pool[g * HD + t] / cnt;

    // fc_initial: Linear(1,192) + LN + ReLU
    float iv = ie[g] * fciW[t] + fcib[t];
    float mu = blk_sum(iv, red) * (1.0f / HD);
    float dv = iv - mu;
    float var = blk_sum(dv * dv, red) * (1.0f / HD);
    float rstd = rsqrtf(var + 1e-5f);
    zin[HD + t] = fmaxf(dv * rstd * fcig[t] + fcilb[t], 0.f);
    __syncthreads();

    // fc1: 384 -> 192, LN, ReLU
    float a = fc1b[t];
    for (int k = 0; k < 2 * HD; k++) a += zin[k] * fc1W[k * HD + t];
    mu = blk_sum(a, red) * (1.0f / HD);
    dv = a - mu;
    var = blk_sum(dv * dv, red) * (1.0f / HD);
    rstd = rsqrtf(var + 1e-5f);
    buf[t] = fmaxf(dv * rstd * fc1g[t] + fc1lb[t], 0.f);
    __syncthreads();

    // fc2: 192 -> 96, LN, ReLU
    float a2 = 0.f;
    if (t < 96) {
        a2 = fc2b[t];
        for (int k = 0; k < HD; k++) a2 += buf[k] * fc2W[k * 96 + t];
    }
    mu = blk_sum(t < 96 ? a2 : 0.f, red) * (1.0f / 96.0f);
    dv = a2 - mu;
    var = blk_sum(t < 96 ? dv * dv : 0.f, red) * (1.0f / 96.0f);
    rstd = rsqrtf(var + 1e-5f);
    float r2 = 0.f;
    if (t < 96) r2 = fmaxf(dv * rstd * fc2g[t] + fc2lb[t], 0.f);

    // fc3: 96 -> 1
    float p3 = (t < 96) ? r2 * fc3W[t] : 0.f;
    float tot = blk_sum(p3, red);
    if (t == 0) out[g] = tot + fc3b[0];
}

// ---------------- launch ------------------------------------------------------
extern "C" void kernel_launch(void* const* d_in, const int* in_sizes, int n_in,
                              void* d_out, int out_size) {
    const float* x    = (const float*)d_in[0];
    const int*   ei   = (const int*)d_in[1];
    const float* ew   = (const float*)d_in[2];
    const int*   batch= (const int*)d_in[3];
    const float* ie   = (const float*)d_in[4];
    const float* Wp   = (const float*)d_in[5];
    const float* bp   = (const float*)d_in[6];
    const float* Wq   = (const float*)d_in[7];
    const float* bq   = (const float*)d_in[8];
    const float* Wk   = (const float*)d_in[9];
    const float* bk   = (const float*)d_in[10];
    const float* Wv   = (const float*)d_in[11];
    const float* bv   = (const float*)d_in[12];
    const float* We   = (const float*)d_in[13];
    const float* Ws   = (const float*)d_in[14];
    const float* bs   = (const float*)d_in[15];
    const float* lng  = (const float*)d_in[16];
    const float* lnb  = (const float*)d_in[17];
    const float* fciW = (const float*)d_in[18];
    const float* fcib = (const float*)d_in[19];
    const float* fcig = (const float*)d_in[20];
    const float* fcilb= (const float*)d_in[21];
    const float* fc1W = (const float*)d_in[22];
    const float* fc1b = (const float*)d_in[23];
    const float* fc1g = (const float*)d_in[24];
    const float* fc1lb= (const float*)d_in[25];
    const float* fc2W = (const float*)d_in[26];
    const float* fc2b = (const float*)d_in[27];
    const float* fc2g = (const float*)d_in[28];
    const float* fc2lb= (const float*)d_in[29];
    const float* fc3W = (const float*)d_in[30];
    const float* fc3b = (const float*)d_in[31];
    float* out = (float*)d_out;

    const int* src = ei;
    const int* dst = ei + EE;

    proj_kernel<<<(NN * HD + 255) / 256, 256>>>(x, Wp, bp);
    split_w_kernel<<<(12 * KSTEPS * 24 * 32 + 255) / 256, 256>>>(Wq, Wk, Wv, Ws);

    // CSR build (edge_index constant across layers)
    deg_zero_kernel<<<(NN + 255) / 256, 256>>>();
    hist_kernel<<<(EE + 255) / 256, 256>>>(dst);
    scan1_kernel<<<SCAN_BLOCKS, 512>>>();
    scan2_kernel<<<1, 256>>>();
    scan3_kernel<<<(NN + 255) / 256, 256>>>();
    scatter_kernel<<<(EE + 255) / 256, 256>>>(src, dst, ew);

    for (int i = 0; i < 3; i++) {
        split_h_kernel<<<NTILES * KSTEPS * 2 * 32 / 256, 256>>>();
        gemm_tc_kernel<<<dim3(NTILES / 4, 4), 256>>>(i, bq, bk, bv, bs);
        node_attn_kernel<<<(NN + 15) / 16, 256>>>(lng + i * HD, lnb + i * HD, We + i * HD);
    }

    pool_init_kernel<<<(GG * HD + 255) / 256, 256>>>();
    pool_kernel<<<512, HD>>>(batch);
    head_kernel<<<GG, HD>>>(ie, fciW, fcib, fcig, fcilb,
                            fc1W, fc1b, fc1g, fc1lb,
                            fc2W, fc2b, fc2g, fc2lb,
                            fc3W, fc3b, out);
}

// round 13
// speedup vs baseline: 1.1692x; 1.0593x over previous
#include <cuda_runtime.h>
#include <cuda_fp16.h>
#include <math.h>
#include <float.h>
#include <stdint.h>

#define NN 100000
#define EE 400000
#define GG 32
#define HH 6
#define HD 192
#define NTILES 6256          // ceil(100000/16)=6250, padded to multiple of 8
#define KSTEPS 12            // 192/16
#define SCAN_BLOCKS 196      // ceil(100000/512)

// ---------------- scratch (device globals; no allocations allowed) ----------
__device__ float g_h[NN * HD];
__device__ __half g_qh[NN * HD];
__device__ __half g_kh[NN * HD];
__device__ __half g_vh[NN * HD];
__device__ __half g_sh[NN * HD];
__device__ float g_pool[GG * HD];
__device__ float g_cnt[GG];

// CSR (built once; edge_index constant across layers)
__device__ int g_deg[NN];
__device__ int g_off[NN];
__device__ int g_cur[NN];
__device__ int g_bsum[256];
__device__ int2 g_edge[EE];          // (src, edge_weight bits)

// fp16x2 fragment operands for mma.sync, pre-paired as u64 for LDG.64
__device__ unsigned long long g_afrag[(size_t)NTILES * KSTEPS * 2 * 32];   // 38.4MB
__device__ unsigned long long g_wfrag[(size_t)12 * KSTEPS * 24 * 32];      // 0.9MB

// ---------------- helpers ---------------------------------------------------
__device__ __forceinline__ unsigned fp2(float a, float b) {
    unsigned r;
    asm("cvt.rn.f16x2.f32 %0, %1, %2;" : "=r"(r) : "f"(b), "f"(a));
    return r;
}

__device__ __forceinline__ void mma_fp16(float* c, const unsigned* a, const unsigned* b) {
    asm("mma.sync.aligned.m16n8k16.row.col.f32.f16.f16.f32 "
        "{%0,%1,%2,%3}, {%4,%5,%6,%7}, {%8,%9}, {%0,%1,%2,%3};"
        : "+f"(c[0]), "+f"(c[1]), "+f"(c[2]), "+f"(c[3])
        : "r"(a[0]), "r"(a[1]), "r"(a[2]), "r"(a[3]), "r"(b[0]), "r"(b[1]));
}

// block reduce over 192 threads (6 warps)
__device__ __forceinline__ float blk_sum(float v, float* red) {
    int t = threadIdx.x, lane = t & 31, w = t >> 5;
#pragma unroll
    for (int o = 16; o; o >>= 1) v += __shfl_xor_sync(0xffffffffu, v, o);
    __syncthreads();
    if (lane == 0) red[w] = v;
    __syncthreads();
    float s = 0.f;
#pragma unroll
    for (int i = 0; i < 6; i++) s += red[i];
    return s;
}

// ---------------- input projection: h = x @ Wp + bp -------------------------
__global__ void proj_kernel(const float* __restrict__ x,
                            const float* __restrict__ Wp,
                            const float* __restrict__ bp) {
    int i = blockIdx.x * blockDim.x + threadIdx.x;
    if (i >= NN * HD) return;
    int n = i / HD, d = i - n * HD;
    const float* xr = x + n * 4;
    float acc = bp[d];
    acc += xr[0] * Wp[d] + xr[1] * Wp[HD + d] + xr[2] * Wp[2 * HD + d] + xr[3] * Wp[3 * HD + d];
    g_h[i] = acc;
}

// ---------------- CSR build (once per launch) -------------------------------
__global__ void deg_zero_kernel() {
    int i = blockIdx.x * 256 + threadIdx.x;
    if (i < NN) g_deg[i] = 0;
}
__global__ void hist_kernel(const int* __restrict__ dst) {
    int e = blockIdx.x * 256 + threadIdx.x;
    if (e < EE) atomicAdd(&g_deg[dst[e]], 1);
}
__global__ void scan1_kernel() {
    __shared__ int sh[512];
    int i = blockIdx.x * 512 + threadIdx.x;
    int v = (i < NN) ? g_deg[i] : 0;
    sh[threadIdx.x] = v;
    __syncthreads();
#pragma unroll
    for (int o = 1; o < 512; o <<= 1) {
        int t = (threadIdx.x >= o) ? sh[threadIdx.x - o] : 0;
        __syncthreads();
        sh[threadIdx.x] += t;
        __syncthreads();
    }
    if (i < NN) g_off[i] = sh[threadIdx.x] - v;
    if (threadIdx.x == 511) g_bsum[blockIdx.x] = sh[511];
}
__global__ void scan2_kernel() {
    __shared__ int sh[256];
    int v = (threadIdx.x < SCAN_BLOCKS) ? g_bsum[threadIdx.x] : 0;
    sh[threadIdx.x] = v;
    __syncthreads();
#pragma unroll
    for (int o = 1; o < 256; o <<= 1) {
        int t = (threadIdx.x >= o) ? sh[threadIdx.x - o] : 0;
        __syncthreads();
        sh[threadIdx.x] += t;
        __syncthreads();
    }
    g_bsum[threadIdx.x] = sh[threadIdx.x] - v;   // exclusive
}
__global__ void scan3_kernel() {
    int i = blockIdx.x * 256 + threadIdx.x;
    if (i >= NN) return;
    int o = g_off[i] + g_bsum[i >> 9];
    g_off[i] = o;
    g_cur[i] = o;
}
__global__ void scatter_kernel(const int* __restrict__ src, const int* __restrict__ dst,
                               const float* __restrict__ ew) {
    int e = blockIdx.x * 256 + threadIdx.x;
    if (e >= EE) return;
    int d = dst[e];
    int pos = atomicAdd(&g_cur[d], 1);
    g_edge[pos] = make_int2(src[e], __float_as_int(ew[e]));
}

// ---------------- convert h into A-fragment layout (fp16 pairs) -------------
__global__ void split_h_kernel() {
    int t = blockIdx.x * 256 + threadIdx.x;
    int lane = t & 31;
    int p = (t >> 5) & 1;
    int ks = (t >> 6) % KSTEPS;
    int tile = t / (KSTEPS * 2 * 32);
    int row = tile * 16 + (lane >> 2);
    int k = ks * 16 + ((lane & 3) << 1) + (p << 3);
    float x0 = 0.f, x1 = 0.f, x2 = 0.f, x3 = 0.f;
    if (row < NN) {
        const float* q = &g_h[row * HD + k];
        x0 = q[0]; x1 = q[1];
    }
    if (row + 8 < NN) {
        const float* q = &g_h[(row + 8) * HD + k];
        x2 = q[0]; x3 = q[1];
    }
    unsigned lo = fp2(x0, x1);
    unsigned hi = fp2(x2, x3);
    g_afrag[t] = ((unsigned long long)hi << 32) | lo;
}

// ---------------- convert all 12 weight matrices into B-fragment layout -----
__global__ void split_w_kernel(const float* __restrict__ Wq, const float* __restrict__ Wk,
                               const float* __restrict__ Wv, const float* __restrict__ Ws) {
    int t = blockIdx.x * 256 + threadIdx.x;
    if (t >= 12 * KSTEPS * 24 * 32) return;
    int lane = t & 31;
    int nt = (t >> 5) % 24;
    int ks = ((t >> 5) / 24) % KSTEPS;
    int mat = t / (32 * 24 * KSTEPS);
    int n = nt * 8 + (lane >> 2);
    int k = ks * 16 + ((lane & 3) << 1);
    int which = mat & 3, layer = mat >> 2;
    const float* W = (which == 0 ? Wq : which == 1 ? Wk : which == 2 ? Wv : Ws)
                     + (size_t)layer * HD * HD;
    unsigned lo = fp2(W[k * HD + n], W[(k + 1) * HD + n]);
    unsigned hi = fp2(W[(k + 8) * HD + n], W[(k + 9) * HD + n]);
    g_wfrag[t] = ((unsigned long long)hi << 32) | lo;
}

// ---------------- tensor-core GEMM: all 4 matrices per CTA, A in smem -------
// CTA: 256 thr = 8 warps, 3 CTAs/SM. CTA covers 4 m-tiles (64 rows) x N=192.
// A fragments staged ONCE in 24KB smem, reused by all 4 weight matrices.
// warp (wm 0..1, wn 0..3): m32 x n48 per mat.
__global__ __launch_bounds__(256, 3) void gemm_tc_kernel(
    int layer,
    const float* __restrict__ bq, const float* __restrict__ bk,
    const float* __restrict__ bv, const float* __restrict__ bs) {
    __shared__ unsigned long long sA[4 * KSTEPS * 2 * 32];   // 24KB
    int w = threadIdx.x >> 5, lane = threadIdx.x & 31;
    int wm = w & 1, wn = w >> 1;
    int tile0 = blockIdx.x * 4;

    // stage A fragments (contiguous in g_afrag) into smem
    const unsigned long long* __restrict__ Ab =
        g_afrag + (size_t)tile0 * KSTEPS * 2 * 32;
#pragma unroll
    for (int i = 0; i < 12; i++)
        sA[threadIdx.x + i * 256] = __ldg(&Ab[threadIdx.x + i * 256]);
    __syncthreads();

    for (int mat = 0; mat < 4; mat++) {
        const unsigned long long* __restrict__ B =
            g_wfrag + (size_t)(layer * 4 + mat) * KSTEPS * 24 * 32;
        float C[2][6][4];
#pragma unroll
        for (int mt = 0; mt < 2; mt++)
#pragma unroll
            for (int nt = 0; nt < 6; nt++)
#pragma unroll
                for (int i = 0; i < 4; i++) C[mt][nt][i] = 0.f;

#pragma unroll 3
        for (int ks = 0; ks < KSTEPS; ks++) {
            unsigned a[2][4];
#pragma unroll
            for (int mt = 0; mt < 2; mt++) {
                int idx = (((wm * 2 + mt) * KSTEPS + ks) * 2) * 32 + lane;
                unsigned long long v0 = sA[idx];
                unsigned long long v1 = sA[idx + 32];
                a[mt][0] = (unsigned)v0; a[mt][1] = (unsigned)(v0 >> 32);
                a[mt][2] = (unsigned)v1; a[mt][3] = (unsigned)(v1 >> 32);
            }
#pragma unroll
            for (int nt = 0; nt < 6; nt++) {
                int ntg = wn * 6 + nt;
                unsigned long long bv2 = __ldg(&B[((size_t)ks * 24 + ntg) * 32 + lane]);
                unsigned b[2] = {(unsigned)bv2, (unsigned)(bv2 >> 32)};
#pragma unroll
                for (int mt = 0; mt < 2; mt++) mma_fp16(C[mt][nt], a[mt], b);
            }
        }

        const float* Bv = ((mat == 0) ? bq : (mat == 1) ? bk
                         : (mat == 2) ? bv : bs) + layer * HD;
        __half* O = (mat == 0) ? g_qh : (mat == 1) ? g_kh
                  : (mat == 2) ? g_vh : g_sh;
#pragma unroll
        for (int mt = 0; mt < 2; mt++) {
            int r0 = (tile0 + wm * 2 + mt) * 16 + (lane >> 2);
#pragma unroll
            for (int nt = 0; nt < 6; nt++) {
                int c = (wn * 6 + nt) * 8 + (lane & 3) * 2;
                float b0 = Bv[c], b1 = Bv[c + 1];
                if (r0 < NN)
                    *reinterpret_cast<__half2*>(&O[r0 * HD + c]) =
                        __floats2half2_rn(C[mt][nt][0] + b0, C[mt][nt][1] + b1);
                int r1 = r0 + 8;
                if (r1 < NN)
                    *reinterpret_cast<__half2*>(&O[r1 * HD + c]) =
                        __floats2half2_rn(C[mt][nt][2] + b0, C[mt][nt][3] + b1);
            }
        }
    }
}

// ---------------- fused node attention: HALF-WARP per dst node --------------
__global__ __launch_bounds__(256, 3) void node_attn_kernel(
    const float* __restrict__ lnw, const float* __restrict__ lnb,
    const float* __restrict__ We) {
    int wid = threadIdx.x >> 5;
    int lane = threadIdx.x & 31;
    int l = lane & 15;
    int half = lane >> 4;
    int n = blockIdx.x * 16 + wid * 2 + half;
    bool nvalid = n < NN;
    int nn = nvalid ? n : 0;
    int off = g_off[nn];
    int deg = nvalid ? g_deg[nn] : 0;
    int dmax = max(deg, __shfl_xor_sync(0xffffffffu, deg, 16));

    const __half2* Q2 = (const __half2*)g_qh + (size_t)nn * 96;
    const float2* We2 = (const float2*)We;
    float2 q[6], we[6];
#pragma unroll
    for (int j = 0; j < 6; j++) {
        q[j] = __half22float2(Q2[16 * j + l]);
        we[j] = We2[16 * j + l];
    }
    float m[6], z[6];
    float2 va[6];
#pragma unroll
    for (int j = 0; j < 6; j++) {
        m[j] = -FLT_MAX; z[j] = 0.f; va[j] = make_float2(0.f, 0.f);
    }
    const float scale = 0.17677669529663687f;  // 1/sqrt(32)

    int2 e = make_int2(0, 0);
    for (int i = 0; i < dmax; i++) {
        if ((i & 15) == 0) {
            e = (i + l < deg) ? __ldg(&g_edge[off + i + l]) : make_int2(0, 0);
        }
        int s = __shfl_sync(0xffffffffu, e.x, i & 15, 16);
        float w = __int_as_float(__shfl_sync(0xffffffffu, e.y, i & 15, 16));
        bool act = i < deg;

        const __half2* K2 = (const __half2*)g_kh + (size_t)s * 96;
        const __half2* V2 = (const __half2*)g_vh + (size_t)s * 96;
        __half2 kb[6], vb[6];
#pragma unroll
        for (int j = 0; j < 6; j++) {
            kb[j] = __ldg(&K2[16 * j + l]);
            vb[j] = __ldg(&V2[16 * j + l]);
        }
        float acc[6];
#pragma unroll
        for (int j = 0; j < 6; j++) {
            float2 kf = __half22float2(kb[j]);
            acc[j] = q[j].x * (kf.x + w * we[j].x) + q[j].y * (kf.y + w * we[j].y);
        }
#pragma unroll
        for (int o = 8; o; o >>= 1)
#pragma unroll
            for (int j = 0; j < 6; j++)
                acc[j] += __shfl_xor_sync(0xffffffffu, acc[j], o, 16);
#pragma unroll
        for (int j = 0; j < 6; j++) {
            float lgt = acc[j] * scale;
            float mn = act ? fmaxf(m[j], lgt) : m[j];
            float corr = __expf(m[j] - mn);       // inactive: exp(0)=1
            float p = act ? __expf(lgt - mn) : 0.f;
            z[j] = z[j] * corr + p;
            float2 vf = __half22float2(vb[j]);
            va[j].x = va[j].x * corr + p * (vf.x + w * we[j].x);
            va[j].y = va[j].y * corr + p * (vf.y + w * we[j].y);
            m[j] = mn;
        }
    }

    if (!nvalid) return;

    // epilogue: val = va/z + skip; LN over 192 dims (16-lane reduce); relu; h+=
    const __half2* S2 = (const __half2*)g_sh + (size_t)n * 96;
    float2 val[6];
    float s1 = 0.f;
#pragma unroll
    for (int j = 0; j < 6; j++) {
        float inv = (z[j] > 0.f) ? (1.0f / z[j]) : 0.f;
        float2 sv = __half22float2(S2[16 * j + l]);
        val[j].x = va[j].x * inv + sv.x;
        val[j].y = va[j].y * inv + sv.y;
        s1 += val[j].x + val[j].y;
    }
#pragma unroll
    for (int o = 8; o; o >>= 1) s1 += __shfl_xor_sync(0xffffffffu, s1, o, 16);
    float mu = s1 * (1.0f / HD);
    float s2 = 0.f;
#pragma unroll
    for (int j = 0; j < 6; j++) {
        float dx = val[j].x - mu, dy = val[j].y - mu;
        s2 += dx * dx + dy * dy;
    }
#pragma unroll
    for (int o = 8; o; o >>= 1) s2 += __shfl_xor_sync(0xffffffffu, s2, o, 16);
    float rstd = rsqrtf(s2 * (1.0f / HD) + 1e-5f);

    const float2* LG2 = (const float2*)lnw;
    const float2* LB2 = (const float2*)lnb;
    float2* H2 = (float2*)g_h + (size_t)n * 96;
#pragma unroll
    for (int j = 0; j < 6; j++) {
        int idx = 16 * j + l;
        float2 gv = LG2[idx], bv = LB2[idx], hv = H2[idx];
        float yx = (val[j].x - mu) * rstd * gv.x + bv.x;
        float yy = (val[j].y - mu) * rstd * gv.y + bv.y;
        hv.x += fmaxf(yx, 0.f);
        hv.y += fmaxf(yy, 0.f);
        H2[idx] = hv;
    }
}

// ---------------- pooling ----------------------------------------------------
__global__ void pool_init_kernel() {
    int i = blockIdx.x * blockDim.x + threadIdx.x;
    if (i < GG * HD) g_pool[i] = 0.f;
    if (i < GG) g_cnt[i] = 0.f;
}

__global__ void pool_kernel(const int* __restrict__ batch) {
    __shared__ float acc[GG * HD];
    __shared__ float scnt[GG];
    int t = threadIdx.x;  // 192
    for (int i = t; i < GG * HD; i += HD) acc[i] = 0.f;
    if (t < GG) scnt[t] = 0.f;
    __syncthreads();
    int per = (NN + gridDim.x - 1) / gridDim.x;
    int n0 = blockIdx.x * per;
    int n1 = min(n0 + per, NN);
    for (int n = n0; n < n1; n++) {
        int g = batch[n];
        acc[g * HD + t] += g_h[n * HD + t];
        if (t == 0) scnt[g] += 1.f;
    }
    __syncthreads();
    for (int i = t; i < GG * HD; i += HD) atomicAdd(&g_pool[i], acc[i]);
    if (t < GG) atomicAdd(&g_cnt[t], scnt[t]);
}

// ---------------- head MLP (block per graph, 192 threads) -------------------
__global__ void head_kernel(const float* __restrict__ ie,
                            const float* __restrict__ fciW, const float* __restrict__ fcib,
                            const float* __restrict__ fcig, const float* __restrict__ fcilb,
                            const float* __restrict__ fc1W, const float* __restrict__ fc1b,
                            const float* __restrict__ fc1g, const float* __restrict__ fc1lb,
                            const float* __restrict__ fc2W, const float* __restrict__ fc2b,
                            const float* __restrict__ fc2g, const float* __restrict__ fc2lb,
                            const float* __restrict__ fc3W, const float* __restrict__ fc3b,
                            float* __restrict__ out) {
    __shared__ float zin[2 * HD];
    __shared__ float buf[HD];
    __shared__ float red[8];
    int t = threadIdx.x;  // 0..191
    int g = blockIdx.x;

    float cnt = fmaxf(g_cnt[g], 1.f);
    zin[t] = g_pool[g * HD + t] / cnt;

    // fc_initial: Linear(1,192) + LN + ReLU
    float iv = ie[g] * fciW[t] + fcib[t];
    float mu = blk_sum(iv, red) * (1.0f / HD);
    float dv = iv - mu;
    float var = blk_sum(dv * dv, red) * (1.0f / HD);
    float rstd = rsqrtf(var + 1e-5f);
    zin[HD + t] = fmaxf(dv * rstd * fcig[t] + fcilb[t], 0.f);
    __syncthreads();

    // fc1: 384 -> 192, LN, ReLU
    float a = fc1b[t];
    for (int k = 0; k < 2 * HD; k++) a += zin[k] * fc1W[k * HD + t];
    mu = blk_sum(a, red) * (1.0f / HD);
    dv = a - mu;
    var = blk_sum(dv * dv, red) * (1.0f / HD);
    rstd = rsqrtf(var + 1e-5f);
    buf[t] = fmaxf(dv * rstd * fc1g[t] + fc1lb[t], 0.f);
    __syncthreads();

    // fc2: 192 -> 96, LN, ReLU
    float a2 = 0.f;
    if (t < 96) {
        a2 = fc2b[t];
        for (int k = 0; k < HD; k++) a2 += buf[k] * fc2W[k * 96 + t];
    }
    mu = blk_sum(t < 96 ? a2 : 0.f, red) * (1.0f / 96.0f);
    dv = a2 - mu;
    var = blk_sum(t < 96 ? dv * dv : 0.f, red) * (1.0f / 96.0f);
    rstd = rsqrtf(var + 1e-5f);
    float r2 = 0.f;
    if (t < 96) r2 = fmaxf(dv * rstd * fc2g[t] + fc2lb[t], 0.f);

    // fc3: 96 -> 1
    float p3 = (t < 96) ? r2 * fc3W[t] : 0.f;
    float tot = blk_sum(p3, red);
    if (t == 0) out[g] = tot + fc3b[0];
}

// ---------------- launch ------------------------------------------------------
extern "C" void kernel_launch(void* const* d_in, const int* in_sizes, int n_in,
                              void* d_out, int out_size) {
    const float* x    = (const float*)d_in[0];
    const int*   ei   = (const int*)d_in[1];
    const float* ew   = (const float*)d_in[2];
    const int*   batch= (const int*)d_in[3];
    const float* ie   = (const float*)d_in[4];
    const float* Wp   = (const float*)d_in[5];
    const float* bp   = (const float*)d_in[6];
    const float* Wq   = (const float*)d_in[7];
    const float* bq   = (const float*)d_in[8];
    const float* Wk   = (const float*)d_in[9];
    const float* bk   = (const float*)d_in[10];
    const float* Wv   = (const float*)d_in[11];
    const float* bv   = (const float*)d_in[12];
    const float* We   = (const float*)d_in[13];
    const float* Ws   = (const float*)d_in[14];
    const float* bs   = (const float*)d_in[15];
    const float* lng  = (const float*)d_in[16];
    const float* lnb  = (const float*)d_in[17];
    const float* fciW = (const float*)d_in[18];
    const float* fcib = (const float*)d_in[19];
    const float* fcig = (const float*)d_in[20];
    const float* fcilb= (const float*)d_in[21];
    const float* fc1W = (const float*)d_in[22];
    const float* fc1b = (const float*)d_in[23];
    const float* fc1g = (const float*)d_in[24];
    const float* fc1lb= (const float*)d_in[25];
    const float* fc2W = (const float*)d_in[26];
    const float* fc2b = (const float*)d_in[27];
    const float* fc2g = (const float*)d_in[28];
    const float* fc2lb= (const float*)d_in[29];
    const float* fc3W = (const float*)d_in[30];
    const float* fc3b = (const float*)d_in[31];
    float* out = (float*)d_out;

    const int* src = ei;
    const int* dst = ei + EE;

    // order chosen so gemm_tc_kernel is the 4th launch (profiled slot)
    proj_kernel<<<(NN * HD + 255) / 256, 256>>>(x, Wp, bp);
    split_w_kernel<<<(12 * KSTEPS * 24 * 32 + 255) / 256, 256>>>(Wq, Wk, Wv, Ws);
    split_h_kernel<<<NTILES * KSTEPS * 2 * 32 / 256, 256>>>();
    gemm_tc_kernel<<<NTILES / 4, 256>>>(0, bq, bk, bv, bs);

    // CSR build (edge_index constant across layers)
    deg_zero_kernel<<<(NN + 255) / 256, 256>>>();
    hist_kernel<<<(EE + 255) / 256, 256>>>(dst);
    scan1_kernel<<<SCAN_BLOCKS, 512>>>();
    scan2_kernel<<<1, 256>>>();
    scan3_kernel<<<(NN + 255) / 256, 256>>>();
    scatter_kernel<<<(EE + 255) / 256, 256>>>(src, dst, ew);

    node_attn_kernel<<<(NN + 15) / 16, 256>>>(lng, lnb, We);

    for (int i = 1; i < 3; i++) {
        split_h_kernel<<<NTILES * KSTEPS * 2 * 32 / 256, 256>>>();
        gemm_tc_kernel<<<NTILES / 4, 256>>>(i, bq, bk, bv, bs);
        node_attn_kernel<<<(NN + 15) / 16, 256>>>(lng + i * HD, lnb + i * HD, We + i * HD);
    }

    pool_init_kernel<<<(GG * HD + 255) / 256, 256>>>();
    pool_kernel<<<512, HD>>>(batch);
    head_kernel<<<GG, HD>>>(ie, fciW, fcib, fcig, fcilb,
                            fc1W, fc1b, fc1g, fc1lb,
                            fc2W, fc2b, fc2g, fc2lb,
                            fc3W, fc3b, out);
}

// round 14
// speedup vs baseline: 1.2040x; 1.0298x over previous
#include <cuda_runtime.h>
#include <cuda_fp16.h>
#include <math.h>
#include <float.h>
#include <stdint.h>

#define NN 100000
#define EE 400000
#define GG 32
#define HH 6
#define HD 192
#define NT4 1564             // ceil(100000/64) = 1563 -> pad 1564
#define KSTEPS 12            // 192/16
#define SCAN_BLOCKS 196      // ceil(100000/512)

// ---------------- scratch (device globals; no allocations allowed) ----------
__device__ float g_h[NN * HD];
__device__ __half g_qh[NN * HD];
__device__ __half g_kh[NN * HD];
__device__ __half g_vh[NN * HD];
__device__ __half g_sh[NN * HD];
__device__ float g_pool[GG * HD];
__device__ float g_cnt[GG];

// CSR (built once; edge_index constant across layers)
__device__ int g_deg[NN];
__device__ int g_off[NN];
__device__ int g_cur[NN];
__device__ int g_bsum[256];
__device__ int2 g_edge[EE];          // (src, edge_weight bits)

// fp16x2 B-fragment operands for mma.sync, pre-paired as u64 for LDG.64
__device__ unsigned long long g_wfrag[(size_t)12 * KSTEPS * 24 * 32];      // 0.9MB

// ---------------- helpers ---------------------------------------------------
__device__ __forceinline__ unsigned fp2(float a, float b) {
    unsigned r;
    asm("cvt.rn.f16x2.f32 %0, %1, %2;" : "=r"(r) : "f"(b), "f"(a));
    return r;
}

__device__ __forceinline__ void mma_fp16(float* c, const unsigned* a, const unsigned* b) {
    asm("mma.sync.aligned.m16n8k16.row.col.f32.f16.f16.f32 "
        "{%0,%1,%2,%3}, {%4,%5,%6,%7}, {%8,%9}, {%0,%1,%2,%3};"
        : "+f"(c[0]), "+f"(c[1]), "+f"(c[2]), "+f"(c[3])
        : "r"(a[0]), "r"(a[1]), "r"(a[2]), "r"(a[3]), "r"(b[0]), "r"(b[1]));
}

// block reduce over 192 threads (6 warps)
__device__ __forceinline__ float blk_sum(float v, float* red) {
    int t = threadIdx.x, lane = t & 31, w = t >> 5;
#pragma unroll
    for (int o = 16; o; o >>= 1) v += __shfl_xor_sync(0xffffffffu, v, o);
    __syncthreads();
    if (lane == 0) red[w] = v;
    __syncthreads();
    float s = 0.f;
#pragma unroll
    for (int i = 0; i < 6; i++) s += red[i];
    return s;
}

// ---------------- input projection: h = x @ Wp + bp -------------------------
__global__ void proj_kernel(const float* __restrict__ x,
                            const float* __restrict__ Wp,
                            const float* __restrict__ bp) {
    int i = blockIdx.x * blockDim.x + threadIdx.x;
    if (i >= NN * HD) return;
    int n = i / HD, d = i - n * HD;
    const float* xr = x + n * 4;
    float acc = bp[d];
    acc += xr[0] * Wp[d] + xr[1] * Wp[HD + d] + xr[2] * Wp[2 * HD + d] + xr[3] * Wp[3 * HD + d];
    g_h[i] = acc;
}

// ---------------- CSR build (once per launch) -------------------------------
__global__ void deg_zero_kernel() {
    int i = blockIdx.x * 256 + threadIdx.x;
    if (i < NN) g_deg[i] = 0;
}
__global__ void hist_kernel(const int* __restrict__ dst) {
    int e = blockIdx.x * 256 + threadIdx.x;
    if (e < EE) atomicAdd(&g_deg[dst[e]], 1);
}
__global__ void scan1_kernel() {
    __shared__ int sh[512];
    int i = blockIdx.x * 512 + threadIdx.x;
    int v = (i < NN) ? g_deg[i] : 0;
    sh[threadIdx.x] = v;
    __syncthreads();
#pragma unroll
    for (int o = 1; o < 512; o <<= 1) {
        int t = (threadIdx.x >= o) ? sh[threadIdx.x - o] : 0;
        __syncthreads();
        sh[threadIdx.x] += t;
        __syncthreads();
    }
    if (i < NN) g_off[i] = sh[threadIdx.x] - v;
    if (threadIdx.x == 511) g_bsum[blockIdx.x] = sh[511];
}
__global__ void scan2_kernel() {
    __shared__ int sh[256];
    int v = (threadIdx.x < SCAN_BLOCKS) ? g_bsum[threadIdx.x] : 0;
    sh[threadIdx.x] = v;
    __syncthreads();
#pragma unroll
    for (int o = 1; o < 256; o <<= 1) {
        int t = (threadIdx.x >= o) ? sh[threadIdx.x - o] : 0;
        __syncthreads();
        sh[threadIdx.x] += t;
        __syncthreads();
    }
    g_bsum[threadIdx.x] = sh[threadIdx.x] - v;   // exclusive
}
__global__ void scan3_kernel() {
    int i = blockIdx.x * 256 + threadIdx.x;
    if (i >= NN) return;
    int o = g_off[i] + g_bsum[i >> 9];
    g_off[i] = o;
    g_cur[i] = o;
}
__global__ void scatter_kernel(const int* __restrict__ src, const int* __restrict__ dst,
                               const float* __restrict__ ew) {
    int e = blockIdx.x * 256 + threadIdx.x;
    if (e >= EE) return;
    int d = dst[e];
    int pos = atomicAdd(&g_cur[d], 1);
    g_edge[pos] = make_int2(src[e], __float_as_int(ew[e]));
}

// ---------------- convert all 12 weight matrices into B-fragment layout -----
__global__ void split_w_kernel(const float* __restrict__ Wq, const float* __restrict__ Wk,
                               const float* __restrict__ Wv, const float* __restrict__ Ws) {
    int t = blockIdx.x * 256 + threadIdx.x;
    if (t >= 12 * KSTEPS * 24 * 32) return;
    int lane = t & 31;
    int nt = (t >> 5) % 24;
    int ks = ((t >> 5) / 24) % KSTEPS;
    int mat = t / (32 * 24 * KSTEPS);
    int n = nt * 8 + (lane >> 2);
    int k = ks * 16 + ((lane & 3) << 1);
    int which = mat & 3, layer = mat >> 2;
    const float* W = (which == 0 ? Wq : which == 1 ? Wk : which == 2 ? Wv : Ws)
                     + (size_t)layer * HD * HD;
    unsigned lo = fp2(W[k * HD + n], W[(k + 1) * HD + n]);
    unsigned hi = fp2(W[(k + 8) * HD + n], W[(k + 9) * HD + n]);
    g_wfrag[t] = ((unsigned long long)hi << 32) | lo;
}

// ---------------- tensor-core GEMM: all 4 matrices per CTA ------------------
// A fragments converted fp32->fp16 from g_h DIRECTLY during smem staging
// (split_h fused away). CTA = 64 rows x N=192 x 4 matrices; 3 CTAs/SM.
__global__ __launch_bounds__(256, 3) void gemm_tc_kernel(
    int layer,
    const float* __restrict__ bq, const float* __restrict__ bk,
    const float* __restrict__ bv, const float* __restrict__ bs) {
    __shared__ unsigned long long sA[4 * KSTEPS * 2 * 32];   // 24KB
    int w = threadIdx.x >> 5, lane = threadIdx.x & 31;
    int wm = w & 1, wn = w >> 1;
    int tile0 = blockIdx.x * 4;

    // stage A: load fp32 h, convert to fragment-layout fp16 pairs in smem.
    // t = tile*768 + ks*64 + p*32 + lane  (matches consumption indexing)
#pragma unroll
    for (int i = 0; i < 12; i++) {
        int t = threadIdx.x + i * 256;
        int ln = t & 31;
        int p = (t >> 5) & 1;
        int ks = (t >> 6) % KSTEPS;
        int tile = t / (KSTEPS * 2 * 32);
        int row = (tile0 + tile) * 16 + (ln >> 2);
        int k = ks * 16 + ((ln & 3) << 1) + (p << 3);
        float2 a0 = make_float2(0.f, 0.f), a1 = make_float2(0.f, 0.f);
        if (row < NN) a0 = *(const float2*)&g_h[(size_t)row * HD + k];
        if (row + 8 < NN) a1 = *(const float2*)&g_h[(size_t)(row + 8) * HD + k];
        unsigned lo = fp2(a0.x, a0.y);
        unsigned hi = fp2(a1.x, a1.y);
        sA[t] = ((unsigned long long)hi << 32) | lo;
    }
    __syncthreads();

    for (int mat = 0; mat < 4; mat++) {
        const unsigned long long* __restrict__ B =
            g_wfrag + (size_t)(layer * 4 + mat) * KSTEPS * 24 * 32;
        float C[2][6][4];
#pragma unroll
        for (int mt = 0; mt < 2; mt++)
#pragma unroll
            for (int nt = 0; nt < 6; nt++)
#pragma unroll
                for (int i = 0; i < 4; i++) C[mt][nt][i] = 0.f;

#pragma unroll 3
        for (int ks = 0; ks < KSTEPS; ks++) {
            unsigned a[2][4];
#pragma unroll
            for (int mt = 0; mt < 2; mt++) {
                int idx = (((wm * 2 + mt) * KSTEPS + ks) * 2) * 32 + lane;
                unsigned long long v0 = sA[idx];
                unsigned long long v1 = sA[idx + 32];
                a[mt][0] = (unsigned)v0; a[mt][1] = (unsigned)(v0 >> 32);
                a[mt][2] = (unsigned)v1; a[mt][3] = (unsigned)(v1 >> 32);
            }
#pragma unroll
            for (int nt = 0; nt < 6; nt++) {
                int ntg = wn * 6 + nt;
                unsigned long long bv2 = __ldg(&B[((size_t)ks * 24 + ntg) * 32 + lane]);
                unsigned b[2] = {(unsigned)bv2, (unsigned)(bv2 >> 32)};
#pragma unroll
                for (int mt = 0; mt < 2; mt++) mma_fp16(C[mt][nt], a[mt], b);
            }
        }

        const float* Bv = ((mat == 0) ? bq : (mat == 1) ? bk
                         : (mat == 2) ? bv : bs) + layer * HD;
        __half* O = (mat == 0) ? g_qh : (mat == 1) ? g_kh
                  : (mat == 2) ? g_vh : g_sh;
#pragma unroll
        for (int mt = 0; mt < 2; mt++) {
            int r0 = (tile0 + wm * 2 + mt) * 16 + (lane >> 2);
#pragma unroll
            for (int nt = 0; nt < 6; nt++) {
                int c = (wn * 6 + nt) * 8 + (lane & 3) * 2;
                float b0 = Bv[c], b1 = Bv[c + 1];
                if (r0 < NN)
                    *reinterpret_cast<__half2*>(&O[r0 * HD + c]) =
                        __floats2half2_rn(C[mt][nt][0] + b0, C[mt][nt][1] + b1);
                int r1 = r0 + 8;
                if (r1 < NN)
                    *reinterpret_cast<__half2*>(&O[r1 * HD + c]) =
                        __floats2half2_rn(C[mt][nt][2] + b0, C[mt][nt][3] + b1);
            }
        }
    }
}

// ---------------- fused node attention: HALF-WARP per dst node --------------
__global__ __launch_bounds__(256, 3) void node_attn_kernel(
    const float* __restrict__ lnw, const float* __restrict__ lnb,
    const float* __restrict__ We) {
    int wid = threadIdx.x >> 5;
    int lane = threadIdx.x & 31;
    int l = lane & 15;
    int half = lane >> 4;
    int n = blockIdx.x * 16 + wid * 2 + half;
    bool nvalid = n < NN;
    int nn = nvalid ? n : 0;
    int off = g_off[nn];
    int deg = nvalid ? g_deg[nn] : 0;
    int dmax = max(deg, __shfl_xor_sync(0xffffffffu, deg, 16));

    const __half2* Q2 = (const __half2*)g_qh + (size_t)nn * 96;
    const float2* We2 = (const float2*)We;
    float2 q[6], we[6];
#pragma unroll
    for (int j = 0; j < 6; j++) {
        q[j] = __half22float2(Q2[16 * j + l]);
        we[j] = We2[16 * j + l];
    }
    float m[6], z[6];
    float2 va[6];
#pragma unroll
    for (int j = 0; j < 6; j++) {
        m[j] = -FLT_MAX; z[j] = 0.f; va[j] = make_float2(0.f, 0.f);
    }
    const float scale = 0.17677669529663687f;  // 1/sqrt(32)

    int2 e = make_int2(0, 0);
    for (int i = 0; i < dmax; i++) {
        if ((i & 15) == 0) {
            e = (i + l < deg) ? __ldg(&g_edge[off + i + l]) : make_int2(0, 0);
        }
        int s = __shfl_sync(0xffffffffu, e.x, i & 15, 16);
        float w = __int_as_float(__shfl_sync(0xffffffffu, e.y, i & 15, 16));
        bool act = i < deg;

        const __half2* K2 = (const __half2*)g_kh + (size_t)s * 96;
        const __half2* V2 = (const __half2*)g_vh + (size_t)s * 96;
        __half2 kb[6], vb[6];
#pragma unroll
        for (int j = 0; j < 6; j++) {
            kb[j] = __ldg(&K2[16 * j + l]);
            vb[j] = __ldg(&V2[16 * j + l]);
        }
        float acc[6];
#pragma unroll
        for (int j = 0; j < 6; j++) {
            float2 kf = __half22float2(kb[j]);
            acc[j] = q[j].x * (kf.x + w * we[j].x) + q[j].y * (kf.y + w * we[j].y);
        }
#pragma unroll
        for (int o = 8; o; o >>= 1)
#pragma unroll
            for (int j = 0; j < 6; j++)
                acc[j] += __shfl_xor_sync(0xffffffffu, acc[j], o, 16);
#pragma unroll
        for (int j = 0; j < 6; j++) {
            float lgt = acc[j] * scale;
            float mn = act ? fmaxf(m[j], lgt) : m[j];
            float corr = __expf(m[j] - mn);       // inactive: exp(0)=1
            float p = act ? __expf(lgt - mn) : 0.f;
            z[j] = z[j] * corr + p;
            float2 vf = __half22float2(vb[j]);
            va[j].x = va[j].x * corr + p * (vf.x + w * we[j].x);
            va[j].y = va[j].y * corr + p * (vf.y + w * we[j].y);
            m[j] = mn;
        }
    }

    if (!nvalid) return;

    // epilogue: val = va/z + skip; LN over 192 dims (16-lane reduce); relu; h+=
    const __half2* S2 = (const __half2*)g_sh + (size_t)n * 96;
    float2 val[6];
    float s1 = 0.f;
#pragma unroll
    for (int j = 0; j < 6; j++) {
        float inv = (z[j] > 0.f) ? (1.0f / z[j]) : 0.f;
        float2 sv = __half22float2(S2[16 * j + l]);
        val[j].x = va[j].x * inv + sv.x;
        val[j].y = va[j].y * inv + sv.y;
        s1 += val[j].x + val[j].y;
    }
#pragma unroll
    for (int o = 8; o; o >>= 1) s1 += __shfl_xor_sync(0xffffffffu, s1, o, 16);
    float mu = s1 * (1.0f / HD);
    float s2 = 0.f;
#pragma unroll
    for (int j = 0; j < 6; j++) {
        float dx = val[j].x - mu, dy = val[j].y - mu;
        s2 += dx * dx + dy * dy;
    }
#pragma unroll
    for (int o = 8; o; o >>= 1) s2 += __shfl_xor_sync(0xffffffffu, s2, o, 16);
    float rstd = rsqrtf(s2 * (1.0f / HD) + 1e-5f);

    const float2* LG2 = (const float2*)lnw;
    const float2* LB2 = (const float2*)lnb;
    float2* H2 = (float2*)g_h + (size_t)n * 96;
#pragma unroll
    for (int j = 0; j < 6; j++) {
        int idx = 16 * j + l;
        float2 gv = LG2[idx], bv = LB2[idx], hv = H2[idx];
        float yx = (val[j].x - mu) * rstd * gv.x + bv.x;
        float yy = (val[j].y - mu) * rstd * gv.y + bv.y;
        hv.x += fmaxf(yx, 0.f);
        hv.y += fmaxf(yy, 0.f);
        H2[idx] = hv;
    }
}

// ---------------- pooling ----------------------------------------------------
__global__ void pool_init_kernel() {
    int i = blockIdx.x * blockDim.x + threadIdx.x;
    if (i < GG * HD) g_pool[i] = 0.f;
    if (i < GG) g_cnt[i] = 0.f;
}

__global__ void pool_kernel(const int* __restrict__ batch) {
    __shared__ float acc[GG * HD];
    __shared__ float scnt[GG];
    int t = threadIdx.x;  // 192
    for (int i = t; i < GG * HD; i += HD) acc[i] = 0.f;
    if (t < GG) scnt[t] = 0.f;
    __syncthreads();
    int per = (NN + gridDim.x - 1) / gridDim.x;
    int n0 = blockIdx.x * per;
    int n1 = min(n0 + per, NN);
    for (int n = n0; n < n1; n++) {
        int g = batch[n];
        acc[g * HD + t] += g_h[n * HD + t];
        if (t == 0) scnt[g] += 1.f;
    }
    __syncthreads();
    for (int i = t; i < GG * HD; i += HD) atomicAdd(&g_pool[i], acc[i]);
    if (t < GG) atomicAdd(&g_cnt[t], scnt[t]);
}

// ---------------- head MLP (block per graph, 192 threads) -------------------
__global__ void head_kernel(const float* __restrict__ ie,
                            const float* __restrict__ fciW, const float* __restrict__ fcib,
                            const float* __restrict__ fcig, const float* __restrict__ fcilb,
                            const float* __restrict__ fc1W, const float* __restrict__ fc1b,
                            const float* __restrict__ fc1g, const float* __restrict__ fc1lb,
                            const float* __restrict__ fc2W, const float* __restrict__ fc2b,
                            const float* __restrict__ fc2g, const float* __restrict__ fc2lb,
                            const float* __restrict__ fc3W, const float* __restrict__ fc3b,
                            float* __restrict__ out) {
    __shared__ float zin[2 * HD];
    __shared__ float buf[HD];
    __shared__ float red[8];
    int t = threadIdx.x;  // 0..191
    int g = blockIdx.x;

    float cnt = fmaxf(g_cnt[g], 1.f);
    zin[t] = g_pool[g * HD + t] / cnt;

    // fc_initial: Linear(1,192) + LN + ReLU
    float iv = ie[g] * fciW[t] + fcib[t];
    float mu = blk_sum(iv, red) * (1.0f / HD);
    float dv = iv - mu;
    float var = blk_sum(dv * dv, red) * (1.0f / HD);
    float rstd = rsqrtf(var + 1e-5f);
    zin[HD + t] = fmaxf(dv * rstd * fcig[t] + fcilb[t], 0.f);
    __syncthreads();

    // fc1: 384 -> 192, LN, ReLU
    float a = fc1b[t];
    for (int k = 0; k < 2 * HD; k++) a += zin[k] * fc1W[k * HD + t];
    mu = blk_sum(a, red) * (1.0f / HD);
    dv = a - mu;
    var = blk_sum(dv * dv, red) * (1.0f / HD);
    rstd = rsqrtf(var + 1e-5f);
    buf[t] = fmaxf(dv * rstd * fc1g[t] + fc1lb[t], 0.f);
    __syncthreads();

    // fc2: 192 -> 96, LN, ReLU
    float a2 = 0.f;
    if (t < 96) {
        a2 = fc2b[t];
        for (int k = 0; k < HD; k++) a2 += buf[k] * fc2W[k * 96 + t];
    }
    mu = blk_sum(t < 96 ? a2 : 0.f, red) * (1.0f / 96.0f);
    dv = a2 - mu;
    var = blk_sum(t < 96 ? dv * dv : 0.f, red) * (1.0f / 96.0f);
    rstd = rsqrtf(var + 1e-5f);
    float r2 = 0.f;
    if (t < 96) r2 = fmaxf(dv * rstd * fc2g[t] + fc2lb[t], 0.f);

    // fc3: 96 -> 1
    float p3 = (t < 96) ? r2 * fc3W[t] : 0.f;
    float tot = blk_sum(p3, red);
    if (t == 0) out[g] = tot + fc3b[0];
}

// ---------------- launch ------------------------------------------------------
extern "C" void kernel_launch(void* const* d_in, const int* in_sizes, int n_in,
                              void* d_out, int out_size) {
    const float* x    = (const float*)d_in[0];
    const int*   ei   = (const int*)d_in[1];
    const float* ew   = (const float*)d_in[2];
    const int*   batch= (const int*)d_in[3];
    const float* ie   = (const float*)d_in[4];
    const float* Wp   = (const float*)d_in[5];
    const float* bp   = (const float*)d_in[6];
    const float* Wq   = (const float*)d_in[7];
    const float* bq   = (const float*)d_in[8];
    const float* Wk   = (const float*)d_in[9];
    const float* bk   = (const float*)d_in[10];
    const float* Wv   = (const float*)d_in[11];
    const float* bv   = (const float*)d_in[12];
    const float* We   = (const float*)d_in[13];
    const float* Ws   = (const float*)d_in[14];
    const float* bs   = (const float*)d_in[15];
    const float* lng  = (const float*)d_in[16];
    const float* lnb  = (const float*)d_in[17];
    const float* fciW = (const float*)d_in[18];
    const float* fcib = (const float*)d_in[19];
    const float* fcig = (const float*)d_in[20];
    const float* fcilb= (const float*)d_in[21];
    const float* fc1W = (const float*)d_in[22];
    const float* fc1b = (const float*)d_in[23];
    const float* fc1g = (const float*)d_in[24];
    const float* fc1lb= (const float*)d_in[25];
    const float* fc2W = (const float*)d_in[26];
    const float* fc2b = (const float*)d_in[27];
    const float* fc2g = (const float*)d_in[28];
    const float* fc2lb= (const float*)d_in[29];
    const float* fc3W = (const float*)d_in[30];
    const float* fc3b = (const float*)d_in[31];
    float* out = (float*)d_out;

    const int* src = ei;
    const int* dst = ei + EE;

    // order keeps gemm_tc_kernel in the profiled (4th) slot
    proj_kernel<<<(NN * HD + 255) / 256, 256>>>(x, Wp, bp);
    split_w_kernel<<<(12 * KSTEPS * 24 * 32 + 255) / 256, 256>>>(Wq, Wk, Wv, Ws);
    deg_zero_kernel<<<(NN + 255) / 256, 256>>>();
    gemm_tc_kernel<<<NT4, 256>>>(0, bq, bk, bv, bs);

    hist_kernel<<<(EE + 255) / 256, 256>>>(dst);
    scan1_kernel<<<SCAN_BLOCKS, 512>>>();
    scan2_kernel<<<1, 256>>>();
    scan3_kernel<<<(NN + 255) / 256, 256>>>();
    scatter_kernel<<<(EE + 255) / 256, 256>>>(src, dst, ew);

    node_attn_kernel<<<(NN + 15) / 16, 256>>>(lng, lnb, We);

    for (int i = 1; i < 3; i++) {
        gemm_tc_kernel<<<NT4, 256>>>(i, bq, bk, bv, bs);
        node_attn_kernel<<<(NN + 15) / 16, 256>>>(lng + i * HD, lnb + i * HD, We + i * HD);
    }

    pool_init_kernel<<<(GG * HD + 255) / 256, 256>>>();
    pool_kernel<<<512, HD>>>(batch);
    head_kernel<<<GG, HD>>>(ie, fciW, fcib, fcig, fcilb,
                            fc1W, fc1b, fc1g, fc1lb,
                            fc2W, fc2b, fc2g, fc2lb,
                            fc3W, fc3b, out);
}

// round 15
// speedup vs baseline: 1.2053x; 1.0010x over previous
#include <cuda_runtime.h>
#include <cuda_fp16.h>
#include <math.h>
#include <float.h>
#include <stdint.h>

#define NN 100000
#define EE 400000
#define GG 32
#define HH 6
#define HD 192
#define NT4 1564             // ceil(100000/64) = 1563 -> pad 1564
#define KSTEPS 12            // 192/16
#define SCAN_BLOCKS 196      // ceil(100000/512)

// ---------------- scratch (device globals; no allocations allowed) ----------
__device__ float g_h[NN * HD];
__device__ __half g_qh[NN * HD];
__device__ __half g_kh[NN * HD];
__device__ __half g_vh[NN * HD];
__device__ __half g_sh[NN * HD];
__device__ float g_pool[GG * HD];
__device__ float g_cnt[GG];

// CSR (built once; edge_index constant across layers)
__device__ int g_deg[NN];
__device__ int g_off[NN];
__device__ int g_cur[NN];
__device__ int g_bsum[256];
__device__ int2 g_edge[EE];          // (src, edge_weight bits)

// fp16x2 B-fragment operands for mma.sync, pre-paired as u64 for LDG.64
__device__ unsigned long long g_wfrag[(size_t)12 * KSTEPS * 24 * 32];      // 0.9MB

// ---------------- helpers ---------------------------------------------------
__device__ __forceinline__ unsigned fp2(float a, float b) {
    unsigned r;
    asm("cvt.rn.f16x2.f32 %0, %1, %2;" : "=r"(r) : "f"(b), "f"(a));
    return r;
}

__device__ __forceinline__ void mma_fp16(float* c, const unsigned* a, const unsigned* b) {
    asm("mma.sync.aligned.m16n8k16.row.col.f32.f16.f16.f32 "
        "{%0,%1,%2,%3}, {%4,%5,%6,%7}, {%8,%9}, {%0,%1,%2,%3};"
        : "+f"(c[0]), "+f"(c[1]), "+f"(c[2]), "+f"(c[3])
        : "r"(a[0]), "r"(a[1]), "r"(a[2]), "r"(a[3]), "r"(b[0]), "r"(b[1]));
}

// block reduce over 192 threads (6 warps)
__device__ __forceinline__ float blk_sum(float v, float* red) {
    int t = threadIdx.x, lane = t & 31, w = t >> 5;
#pragma unroll
    for (int o = 16; o; o >>= 1) v += __shfl_xor_sync(0xffffffffu, v, o);
    __syncthreads();
    if (lane == 0) red[w] = v;
    __syncthreads();
    float s = 0.f;
#pragma unroll
    for (int i = 0; i < 6; i++) s += red[i];
    return s;
}

// ---------------- input projection: h = x @ Wp + bp -------------------------
__global__ void proj_kernel(const float* __restrict__ x,
                            const float* __restrict__ Wp,
                            const float* __restrict__ bp) {
    int i = blockIdx.x * blockDim.x + threadIdx.x;
    if (i >= NN * HD) return;
    int n = i / HD, d = i - n * HD;
    const float* xr = x + n * 4;
    float acc = bp[d];
    acc += xr[0] * Wp[d] + xr[1] * Wp[HD + d] + xr[2] * Wp[2 * HD + d] + xr[3] * Wp[3 * HD + d];
    g_h[i] = acc;
}

// ---------------- CSR build (once per launch) -------------------------------
__global__ void deg_zero_kernel() {
    int i = blockIdx.x * 256 + threadIdx.x;
    if (i < NN) g_deg[i] = 0;
}
__global__ void hist_kernel(const int* __restrict__ dst) {
    int e = blockIdx.x * 256 + threadIdx.x;
    if (e < EE) atomicAdd(&g_deg[dst[e]], 1);
}
__global__ void scan1_kernel() {
    __shared__ int sh[512];
    int i = blockIdx.x * 512 + threadIdx.x;
    int v = (i < NN) ? g_deg[i] : 0;
    sh[threadIdx.x] = v;
    __syncthreads();
#pragma unroll
    for (int o = 1; o < 512; o <<= 1) {
        int t = (threadIdx.x >= o) ? sh[threadIdx.x - o] : 0;
        __syncthreads();
        sh[threadIdx.x] += t;
        __syncthreads();
    }
    if (i < NN) g_off[i] = sh[threadIdx.x] - v;
    if (threadIdx.x == 511) g_bsum[blockIdx.x] = sh[511];
}
__global__ void scan2_kernel() {
    __shared__ int sh[256];
    int v = (threadIdx.x < SCAN_BLOCKS) ? g_bsum[threadIdx.x] : 0;
    sh[threadIdx.x] = v;
    __syncthreads();
#pragma unroll
    for (int o = 1; o < 256; o <<= 1) {
        int t = (threadIdx.x >= o) ? sh[threadIdx.x - o] : 0;
        __syncthreads();
        sh[threadIdx.x] += t;
        __syncthreads();
    }
    g_bsum[threadIdx.x] = sh[threadIdx.x] - v;   // exclusive
}
__global__ void scan3_kernel() {
    int i = blockIdx.x * 256 + threadIdx.x;
    if (i >= NN) return;
    int o = g_off[i] + g_bsum[i >> 9];
    g_off[i] = o;
    g_cur[i] = o;
}
__global__ void scatter_kernel(const int* __restrict__ src, const int* __restrict__ dst,
                               const float* __restrict__ ew) {
    int e = blockIdx.x * 256 + threadIdx.x;
    if (e >= EE) return;
    int d = dst[e];
    int pos = atomicAdd(&g_cur[d], 1);
    g_edge[pos] = make_int2(src[e], __float_as_int(ew[e]));
}

// ---------------- convert all 12 weight matrices into B-fragment layout -----
__global__ void split_w_kernel(const float* __restrict__ Wq, const float* __restrict__ Wk,
                               const float* __restrict__ Wv, const float* __restrict__ Ws) {
    int t = blockIdx.x * 256 + threadIdx.x;
    if (t >= 12 * KSTEPS * 24 * 32) return;
    int lane = t & 31;
    int nt = (t >> 5) % 24;
    int ks = ((t >> 5) / 24) % KSTEPS;
    int mat = t / (32 * 24 * KSTEPS);
    int n = nt * 8 + (lane >> 2);
    int k = ks * 16 + ((lane & 3) << 1);
    int which = mat & 3, layer = mat >> 2;
    const float* W = (which == 0 ? Wq : which == 1 ? Wk : which == 2 ? Wv : Ws)
                     + (size_t)layer * HD * HD;
    unsigned lo = fp2(W[k * HD + n], W[(k + 1) * HD + n]);
    unsigned hi = fp2(W[(k + 8) * HD + n], W[(k + 9) * HD + n]);
    g_wfrag[t] = ((unsigned long long)hi << 32) | lo;
}

// ---------------- tensor-core GEMM: all 4 matrices per CTA ------------------
// A fragments converted fp32->fp16 from g_h DIRECTLY during smem staging
// (split_h fused away). CTA = 64 rows x N=192 x 4 matrices; 3 CTAs/SM.
__global__ __launch_bounds__(256, 3) void gemm_tc_kernel(
    int layer,
    const float* __restrict__ bq, const float* __restrict__ bk,
    const float* __restrict__ bv, const float* __restrict__ bs) {
    __shared__ unsigned long long sA[4 * KSTEPS * 2 * 32];   // 24KB
    int w = threadIdx.x >> 5, lane = threadIdx.x & 31;
    int wm = w & 1, wn = w >> 1;
    int tile0 = blockIdx.x * 4;

    // stage A: load fp32 h, convert to fragment-layout fp16 pairs in smem.
    // t = tile*768 + ks*64 + p*32 + lane  (matches consumption indexing)
#pragma unroll
    for (int i = 0; i < 12; i++) {
        int t = threadIdx.x + i * 256;
        int ln = t & 31;
        int p = (t >> 5) & 1;
        int ks = (t >> 6) % KSTEPS;
        int tile = t / (KSTEPS * 2 * 32);
        int row = (tile0 + tile) * 16 + (ln >> 2);
        int k = ks * 16 + ((ln & 3) << 1) + (p << 3);
        float2 a0 = make_float2(0.f, 0.f), a1 = make_float2(0.f, 0.f);
        if (row < NN) a0 = *(const float2*)&g_h[(size_t)row * HD + k];
        if (row + 8 < NN) a1 = *(const float2*)&g_h[(size_t)(row + 8) * HD + k];
        unsigned lo = fp2(a0.x, a0.y);
        unsigned hi = fp2(a1.x, a1.y);
        sA[t] = ((unsigned long long)hi << 32) | lo;
    }
    __syncthreads();

    for (int mat = 0; mat < 4; mat++) {
        const unsigned long long* __restrict__ B =
            g_wfrag + (size_t)(layer * 4 + mat) * KSTEPS * 24 * 32;
        float C[2][6][4];
#pragma unroll
        for (int mt = 0; mt < 2; mt++)
#pragma unroll
            for (int nt = 0; nt < 6; nt++)
#pragma unroll
                for (int i = 0; i < 4; i++) C[mt][nt][i] = 0.f;

#pragma unroll 3
        for (int ks = 0; ks < KSTEPS; ks++) {
            unsigned a[2][4];
#pragma unroll
            for (int mt = 0; mt < 2; mt++) {
                int idx = (((wm * 2 + mt) * KSTEPS + ks) * 2) * 32 + lane;
                unsigned long long v0 = sA[idx];
                unsigned long long v1 = sA[idx + 32];
                a[mt][0] = (unsigned)v0; a[mt][1] = (unsigned)(v0 >> 32);
                a[mt][2] = (unsigned)v1; a[mt][3] = (unsigned)(v1 >> 32);
            }
#pragma unroll
            for (int nt = 0; nt < 6; nt++) {
                int ntg = wn * 6 + nt;
                unsigned long long bv2 = __ldg(&B[((size_t)ks * 24 + ntg) * 32 + lane]);
                unsigned b[2] = {(unsigned)bv2, (unsigned)(bv2 >> 32)};
#pragma unroll
                for (int mt = 0; mt < 2; mt++) mma_fp16(C[mt][nt], a[mt], b);
            }
        }

        const float* Bv = ((mat == 0) ? bq : (mat == 1) ? bk
                         : (mat == 2) ? bv : bs) + layer * HD;
        __half* O = (mat == 0) ? g_qh : (mat == 1) ? g_kh
                  : (mat == 2) ? g_vh : g_sh;
#pragma unroll
        for (int mt = 0; mt < 2; mt++) {
            int r0 = (tile0 + wm * 2 + mt) * 16 + (lane >> 2);
#pragma unroll
            for (int nt = 0; nt < 6; nt++) {
                int c = (wn * 6 + nt) * 8 + (lane & 3) * 2;
                float b0 = Bv[c], b1 = Bv[c + 1];
                if (r0 < NN)
                    *reinterpret_cast<__half2*>(&O[r0 * HD + c]) =
                        __floats2half2_rn(C[mt][nt][0] + b0, C[mt][nt][1] + b1);
                int r1 = r0 + 8;
                if (r1 < NN)
                    *reinterpret_cast<__half2*>(&O[r1 * HD + c]) =
                        __floats2half2_rn(C[mt][nt][2] + b0, C[mt][nt][3] + b1);
            }
        }
    }
}

// ---------------- fused node attention: HALF-WARP per dst node --------------
__global__ __launch_bounds__(256, 3) void node_attn_kernel(
    const float* __restrict__ lnw, const float* __restrict__ lnb,
    const float* __restrict__ We) {
    int wid = threadIdx.x >> 5;
    int lane = threadIdx.x & 31;
    int l = lane & 15;
    int half = lane >> 4;
    int n = blockIdx.x * 16 + wid * 2 + half;
    bool nvalid = n < NN;
    int nn = nvalid ? n : 0;
    int off = g_off[nn];
    int deg = nvalid ? g_deg[nn] : 0;
    int dmax = max(deg, __shfl_xor_sync(0xffffffffu, deg, 16));

    const __half2* Q2 = (const __half2*)g_qh + (size_t)nn * 96;
    const float2* We2 = (const float2*)We;
    float2 q[6], we[6];
#pragma unroll
    for (int j = 0; j < 6; j++) {
        q[j] = __half22float2(Q2[16 * j + l]);
        we[j] = We2[16 * j + l];
    }
    float m[6], z[6];
    float2 va[6];
#pragma unroll
    for (int j = 0; j < 6; j++) {
        m[j] = -FLT_MAX; z[j] = 0.f; va[j] = make_float2(0.f, 0.f);
    }
    const float scale = 0.17677669529663687f;  // 1/sqrt(32)

    int2 e = make_int2(0, 0);
    for (int i = 0; i < dmax; i++) {
        if ((i & 15) == 0) {
            e = (i + l < deg) ? __ldg(&g_edge[off + i + l]) : make_int2(0, 0);
        }
        int s = __shfl_sync(0xffffffffu, e.x, i & 15, 16);
        float w = __int_as_float(__shfl_sync(0xffffffffu, e.y, i & 15, 16));
        bool act = i < deg;

        const __half2* K2 = (const __half2*)g_kh + (size_t)s * 96;
        const __half2* V2 = (const __half2*)g_vh + (size_t)s * 96;
        __half2 kb[6], vb[6];
#pragma unroll
        for (int j = 0; j < 6; j++) {
            kb[j] = __ldg(&K2[16 * j + l]);
            vb[j] = __ldg(&V2[16 * j + l]);
        }
        float acc[6];
#pragma unroll
        for (int j = 0; j < 6; j++) {
            float2 kf = __half22float2(kb[j]);
            acc[j] = q[j].x * (kf.x + w * we[j].x) + q[j].y * (kf.y + w * we[j].y);
        }
#pragma unroll
        for (int o = 8; o; o >>= 1)
#pragma unroll
            for (int j = 0; j < 6; j++)
                acc[j] += __shfl_xor_sync(0xffffffffu, acc[j], o, 16);
#pragma unroll
        for (int j = 0; j < 6; j++) {
            float lgt = acc[j] * scale;
            float mn = act ? fmaxf(m[j], lgt) : m[j];
            float corr = __expf(m[j] - mn);       // inactive: exp(0)=1
            float p = act ? __expf(lgt - mn) : 0.f;
            z[j] = z[j] * corr + p;
            float2 vf = __half22float2(vb[j]);
            va[j].x = va[j].x * corr + p * (vf.x + w * we[j].x);
            va[j].y = va[j].y * corr + p * (vf.y + w * we[j].y);
            m[j] = mn;
        }
    }

    if (!nvalid) return;

    // epilogue: val = va/z + skip; LN over 192 dims (16-lane reduce); relu; h+=
    const __half2* S2 = (const __half2*)g_sh + (size_t)n * 96;
    float2 val[6];
    float s1 = 0.f;
#pragma unroll
    for (int j = 0; j < 6; j++) {
        float inv = (z[j] > 0.f) ? (1.0f / z[j]) : 0.f;
        float2 sv = __half22float2(S2[16 * j + l]);
        val[j].x = va[j].x * inv + sv.x;
        val[j].y = va[j].y * inv + sv.y;
        s1 += val[j].x + val[j].y;
    }
#pragma unroll
    for (int o = 8; o; o >>= 1) s1 += __shfl_xor_sync(0xffffffffu, s1, o, 16);
    float mu = s1 * (1.0f / HD);
    float s2 = 0.f;
#pragma unroll
    for (int j = 0; j < 6; j++) {
        float dx = val[j].x - mu, dy = val[j].y - mu;
        s2 += dx * dx + dy * dy;
    }
#pragma unroll
    for (int o = 8; o; o >>= 1) s2 += __shfl_xor_sync(0xffffffffu, s2, o, 16);
    float rstd = rsqrtf(s2 * (1.0f / HD) + 1e-5f);

    const float2* LG2 = (const float2*)lnw;
    const float2* LB2 = (const float2*)lnb;
    float2* H2 = (float2*)g_h + (size_t)n * 96;
#pragma unroll
    for (int j = 0; j < 6; j++) {
        int idx = 16 * j + l;
        float2 gv = LG2[idx], bv = LB2[idx], hv = H2[idx];
        float yx = (val[j].x - mu) * rstd * gv.x + bv.x;
        float yy = (val[j].y - mu) * rstd * gv.y + bv.y;
        hv.x += fmaxf(yx, 0.f);
        hv.y += fmaxf(yy, 0.f);
        H2[idx] = hv;
    }
}

// ---------------- pooling ----------------------------------------------------
__global__ void pool_init_kernel() {
    int i = blockIdx.x * blockDim.x + threadIdx.x;
    if (i < GG * HD) g_pool[i] = 0.f;
    if (i < GG) g_cnt[i] = 0.f;
}

__global__ void pool_kernel(const int* __restrict__ batch) {
    __shared__ float acc[GG * HD];
    __shared__ float scnt[GG];
    int t = threadIdx.x;  // 192
    for (int i = t; i < GG * HD; i += HD) acc[i] = 0.f;
    if (t < GG) scnt[t] = 0.f;
    __syncthreads();
    int per = (NN + gridDim.x - 1) / gridDim.x;
    int n0 = blockIdx.x * per;
    int n1 = min(n0 + per, NN);
    for (int n = n0; n < n1; n++) {
        int g = batch[n];
        acc[g * HD + t] += g_h[n * HD + t];
        if (t == 0) scnt[g] += 1.f;
    }
    __syncthreads();
    for (int i = t; i < GG * HD; i += HD) atomicAdd(&g_pool[i], acc[i]);
    if (t < GG) atomicAdd(&g_cnt[t], scnt[t]);
}

// ---------------- head MLP (block per graph, 192 threads) -------------------
__global__ void head_kernel(const float* __restrict__ ie,
                            const float* __restrict__ fciW, const float* __restrict__ fcib,
                            const float* __restrict__ fcig, const float* __restrict__ fcilb,
                            const float* __restrict__ fc1W, const float* __restrict__ fc1b,
                            const float* __restrict__ fc1g, const float* __restrict__ fc1lb,
                            const float* __restrict__ fc2W, const float* __restrict__ fc2b,
                            const float* __restrict__ fc2g, const float* __restrict__ fc2lb,
                            const float* __restrict__ fc3W, const float* __restrict__ fc3b,
                            float* __restrict__ out) {
    __shared__ float zin[2 * HD];
    __shared__ float buf[HD];
    __shared__ float red[8];
    int t = threadIdx.x;  // 0..191
    int g = blockIdx.x;

    float cnt = fmaxf(g_cnt[g], 1.f);
    zin[t] = g_pool[g * HD + t] / cnt;

    // fc_initial: Linear(1,192) + LN + ReLU
    float iv = ie[g] * fciW[t] + fcib[t];
    float mu = blk_sum(iv, red) * (1.0f / HD);
    float dv = iv - mu;
    float var = blk_sum(dv * dv, red) * (1.0f / HD);
    float rstd = rsqrtf(var + 1e-5f);
    zin[HD + t] = fmaxf(dv * rstd * fcig[t] + fcilb[t], 0.f);
    __syncthreads();

    // fc1: 384 -> 192, LN, ReLU
    float a = fc1b[t];
    for (int k = 0; k < 2 * HD; k++) a += zin[k] * fc1W[k * HD + t];
    mu = blk_sum(a, red) * (1.0f / HD);
    dv = a - mu;
    var = blk_sum(dv * dv, red) * (1.0f / HD);
    rstd = rsqrtf(var + 1e-5f);
    buf[t] = fmaxf(dv * rstd * fc1g[t] + fc1lb[t], 0.f);
    __syncthreads();

    // fc2: 192 -> 96, LN, ReLU
    float a2 = 0.f;
    if (t < 96) {
        a2 = fc2b[t];
        for (int k = 0; k < HD; k++) a2 += buf[k] * fc2W[k * 96 + t];
    }
    mu = blk_sum(t < 96 ? a2 : 0.f, red) * (1.0f / 96.0f);
    dv = a2 - mu;
    var = blk_sum(t < 96 ? dv * dv : 0.f, red) * (1.0f / 96.0f);
    rstd = rsqrtf(var + 1e-5f);
    float r2 = 0.f;
    if (t < 96) r2 = fmaxf(dv * rstd * fc2g[t] + fc2lb[t], 0.f);

    // fc3: 96 -> 1
    float p3 = (t < 96) ? r2 * fc3W[t] : 0.f;
    float tot = blk_sum(p3, red);
    if (t == 0) out[g] = tot + fc3b[0];
}

// ---------------- launch ------------------------------------------------------
extern "C" void kernel_launch(void* const* d_in, const int* in_sizes, int n_in,
                              void* d_out, int out_size) {
    const float* x    = (const float*)d_in[0];
    const int*   ei   = (const int*)d_in[1];
    const float* ew   = (const float*)d_in[2];
    const int*   batch= (const int*)d_in[3];
    const float* ie   = (const float*)d_in[4];
    const float* Wp   = (const float*)d_in[5];
    const float* bp   = (const float*)d_in[6];
    const float* Wq   = (const float*)d_in[7];
    const float* bq   = (const float*)d_in[8];
    const float* Wk   = (const float*)d_in[9];
    const float* bk   = (const float*)d_in[10];
    const float* Wv   = (const float*)d_in[11];
    const float* bv   = (const float*)d_in[12];
    const float* We   = (const float*)d_in[13];
    const float* Ws   = (const float*)d_in[14];
    const float* bs   = (const float*)d_in[15];
    const float* lng  = (const float*)d_in[16];
    const float* lnb  = (const float*)d_in[17];
    const float* fciW = (const float*)d_in[18];
    const float* fcib = (const float*)d_in[19];
    const float* fcig = (const float*)d_in[20];
    const float* fcilb= (const float*)d_in[21];
    const float* fc1W = (const float*)d_in[22];
    const float* fc1b = (const float*)d_in[23];
    const float* fc1g = (const float*)d_in[24];
    const float* fc1lb= (const float*)d_in[25];
    const float* fc2W = (const float*)d_in[26];
    const float* fc2b = (const float*)d_in[27];
    const float* fc2g = (const float*)d_in[28];
    const float* fc2lb= (const float*)d_in[29];
    const float* fc3W = (const float*)d_in[30];
    const float* fc3b = (const float*)d_in[31];
    float* out = (float*)d_out;

    const int* src = ei;
    const int* dst = ei + EE;

    // order keeps gemm_tc_kernel in the profiled (4th) slot
    proj_kernel<<<(NN * HD + 255) / 256, 256>>>(x, Wp, bp);
    split_w_kernel<<<(12 * KSTEPS * 24 * 32 + 255) / 256, 256>>>(Wq, Wk, Wv, Ws);
    deg_zero_kernel<<<(NN + 255) / 256, 256>>>();
    gemm_tc_kernel<<<NT4, 256>>>(0, bq, bk, bv, bs);

    hist_kernel<<<(EE + 255) / 256, 256>>>(dst);
    scan1_kernel<<<SCAN_BLOCKS, 512>>>();
    scan2_kernel<<<1, 256>>>();
    scan3_kernel<<<(NN + 255) / 256, 256>>>();
    scatter_kernel<<<(EE + 255) / 256, 256>>>(src, dst, ew);

    node_attn_kernel<<<(NN + 15) / 16, 256>>>(lng, lnb, We);

    for (int i = 1; i < 3; i++) {
        gemm_tc_kernel<<<NT4, 256>>>(i, bq, bk, bv, bs);
        node_attn_kernel<<<(NN + 15) / 16, 256>>>(lng + i * HD, lnb + i * HD, We + i * HD);
    }

    pool_init_kernel<<<(GG * HD + 255) / 256, 256>>>();
    pool_kernel<<<512, HD>>>(batch);
    head_kernel<<<GG, HD>>>(ie, fciW, fcib, fcig, fcilb,
                            fc1W, fc1b, fc1g, fc1lb,
                            fc2W, fc2b, fc2g, fc2lb,
                            fc3W, fc3b, out);
}